// round 1
// baseline (speedup 1.0000x reference)
#include <cuda_runtime.h>
#include <cuda_bf16.h>
#include <math.h>

// Problem constants
#define BATCH 2
#define SEQ   2048
#define HID   2048
#define NH    32
#define NKV   4
#define HD    128
#define NTOK  (BATCH*SEQ)          // 4096
#define QCOLS (NH*HD)              // 4096
#define KVCOLS (NKV*HD)            // 512

// -------- scratch (device globals: no runtime allocation allowed) --------
__device__ float g_Q[(size_t)NTOK * QCOLS];    // 64 MiB
__device__ float g_K[(size_t)NTOK * KVCOLS];   // 8 MiB
__device__ float g_V[(size_t)NTOK * KVCOLS];   // 8 MiB
__device__ float g_CTX[(size_t)NTOK * QCOLS];  // 64 MiB

// ============================================================================
// SGEMM: C[M,N] = A[M,K] @ B[K,N], all row-major fp32.
// 128x128 block tile, BK=8, 256 threads, 8x8 per-thread tile with interleaved
// fragment mapping (rows tr+16i, cols tc+16j) for conflict-free shared reads.
// ============================================================================
__global__ __launch_bounds__(256, 2)
void sgemm_kernel(const float* __restrict__ A, const float* __restrict__ B,
                  float* __restrict__ C, int M, int N, int K)
{
    __shared__ float As[8][128];     // transposed A tile: As[k][m]
    __shared__ float Bs[8][132];     // Bs[k][n] (padded)

    const int bx = blockIdx.x;       // N tile
    const int by = blockIdx.y;       // M tile
    const int tid = threadIdx.x;
    const int tr = tid >> 4;         // 0..15
    const int tc = tid & 15;         // 0..15

    const float* Ab = A + (size_t)(by * 128) * K;
    const float* Bb = B + (size_t)(bx * 128);

    const int arow  = tid >> 1;            // 0..127
    const int acol4 = (tid & 1) * 4;       // 0 or 4
    const int brow  = tid >> 5;            // 0..7
    const int bcol4 = (tid & 31) * 4;      // 0..124

    float acc[8][8];
    #pragma unroll
    for (int i = 0; i < 8; i++)
        #pragma unroll
        for (int j = 0; j < 8; j++) acc[i][j] = 0.f;

    for (int k0 = 0; k0 < K; k0 += 8) {
        float4 av = *(const float4*)(Ab + (size_t)arow * K + k0 + acol4);
        float4 bv = *(const float4*)(Bb + (size_t)(k0 + brow) * N + bcol4);

        As[acol4 + 0][arow] = av.x;
        As[acol4 + 1][arow] = av.y;
        As[acol4 + 2][arow] = av.z;
        As[acol4 + 3][arow] = av.w;
        *(float4*)&Bs[brow][bcol4] = bv;
        __syncthreads();

        #pragma unroll
        for (int k = 0; k < 8; k++) {
            float af[8], bf[8];
            #pragma unroll
            for (int i = 0; i < 8; i++) af[i] = As[k][tr + 16 * i];
            #pragma unroll
            for (int j = 0; j < 8; j++) bf[j] = Bs[k][tc + 16 * j];
            #pragma unroll
            for (int i = 0; i < 8; i++)
                #pragma unroll
                for (int j = 0; j < 8; j++)
                    acc[i][j] = fmaf(af[i], bf[j], acc[i][j]);
        }
        __syncthreads();
    }

    float* Cb = C + (size_t)(by * 128) * N + bx * 128;
    #pragma unroll
    for (int i = 0; i < 8; i++)
        #pragma unroll
        for (int j = 0; j < 8; j++)
            Cb[(size_t)(tr + 16 * i) * N + tc + 16 * j] = acc[i][j];
}

// ============================================================================
// RMSNorm + RoPE, one block of 128 threads per (token, head).
// X layout: [token][head*128 + d]. In-place.
// ============================================================================
__global__ __launch_bounds__(128)
void rmsrope_kernel(float* __restrict__ X, const float* __restrict__ w,
                    const int* __restrict__ pos, int nheads)
{
    const int blk = blockIdx.x;
    const int token = blk / nheads;
    const int h     = blk % nheads;
    float* x = X + (size_t)token * (nheads * HD) + h * HD;

    const int i = threadIdx.x;
    float v = x[i];

    // sum of squares over 128 lanes
    float ss = v * v;
    #pragma unroll
    for (int m = 16; m; m >>= 1) ss += __shfl_xor_sync(0xffffffffu, ss, m);
    __shared__ float wsum[4];
    if ((i & 31) == 0) wsum[i >> 5] = ss;
    __syncthreads();
    float tot = wsum[0] + wsum[1] + wsum[2] + wsum[3];
    float inv = rsqrtf(tot * (1.0f / 128.0f) + 1e-6f);

    __shared__ float xs[128];
    xs[i] = v * inv * w[i];
    __syncthreads();

    const int p = pos[token];
    const int j = i & 63;
    // inv_freq = 1e6^(-j/64): compute in double, round to fp32 (tracks jax fp32 pow)
    float invf = (float)pow(1.0e6, -(double)j / 64.0);
    float f = (float)p * invf;
    float c, s;
    sincosf(f, &s, &c);
    float xi = xs[i];
    float partner = (i < 64) ? -xs[i + 64] : xs[i - 64];
    x[i] = xi * c + partner * s;
}

// ============================================================================
// Flash attention, fp32, causal. Br=128 q-rows per block, Bc=64 k-rows/tile.
// 256 threads. Per thread: 8 q-rows (ty+16*i), S cols tx+16*j (4), O cols
// tx+16*j (8). grid = (S/128, NH, B).
// ============================================================================
#define QP 132
#define KP 68
#define VP 132
#define PP 68
#define ATTN_SMEM ((128*QP + 128*KP + 64*VP + 128*PP) * 4)

__global__ __launch_bounds__(256, 1)
void attn_kernel(const float* __restrict__ Q, const float* __restrict__ K,
                 const float* __restrict__ V, float* __restrict__ CTX)
{
    extern __shared__ float sm[];
    float* Qs = sm;                    // [128][QP]
    float* Kt = Qs + 128 * QP;         // [128][KP] transposed: Kt[d][c]
    float* Vs = Kt + 128 * KP;         // [64][VP]
    float* Ps = Vs + 64 * VP;          // [128][PP]

    const int qt = gridDim.x - 1 - blockIdx.x;   // reverse order: big tiles first
    const int h  = blockIdx.y;
    const int b  = blockIdx.z;
    const int hk = h >> 3;                        // NH/NKV = 8

    const int tid = threadIdx.x;
    const int ty = tid >> 4;   // 0..15
    const int tx = tid & 15;   // 0..15

    const float scale = 0.08838834764831845f;    // 1/sqrt(128)

    // ---- load Q tile (128 x 128), pre-scaled ----
    {
        const int r  = tid >> 1;            // 0..127
        const int d0 = (tid & 1) * 64;      // 0 or 64
        const float* src = Q + ((size_t)(b * SEQ + qt * 128 + r)) * QCOLS + h * HD + d0;
        float* dst = Qs + r * QP + d0;
        #pragma unroll
        for (int u = 0; u < 16; u++) {
            float4 v = *(const float4*)(src + 4 * u);
            dst[4 * u + 0] = v.x * scale;
            dst[4 * u + 1] = v.y * scale;
            dst[4 * u + 2] = v.z * scale;
            dst[4 * u + 3] = v.w * scale;
        }
    }

    float o[8][8];
    float m[8], l[8];
    #pragma unroll
    for (int i = 0; i < 8; i++) {
        m[i] = -3.0e38f; l[i] = 0.f;
        #pragma unroll
        for (int j = 0; j < 8; j++) o[i][j] = 0.f;
    }

    const int ntiles = 2 * qt + 2;   // k-tiles of 64 covering [0, (qt+1)*128)
    for (int jt = 0; jt < ntiles; jt++) {
        // ---- load K (transposed) and V tiles (64 x 128) ----
        {
            const int c  = tid >> 2;           // 0..63
            const int d0 = (tid & 3) * 32;     // 0,32,64,96
            const size_t tok = (size_t)(b * SEQ + jt * 64 + c);
            const float* ksrc = K + tok * KVCOLS + hk * HD + d0;
            const float* vsrc = V + tok * KVCOLS + hk * HD + d0;
            float* vdst = Vs + c * VP + d0;
            #pragma unroll
            for (int u = 0; u < 8; u++) {
                float4 kv = *(const float4*)(ksrc + 4 * u);
                int d = d0 + 4 * u;
                Kt[(d + 0) * KP + c] = kv.x;
                Kt[(d + 1) * KP + c] = kv.y;
                Kt[(d + 2) * KP + c] = kv.z;
                Kt[(d + 3) * KP + c] = kv.w;
                *(float4*)(vdst + 4 * u) = *(const float4*)(vsrc + 4 * u);
            }
        }
        __syncthreads();

        // ---- S = Qs @ Kt : per thread 8 rows x 4 cols ----
        float s[8][4];
        #pragma unroll
        for (int i = 0; i < 8; i++)
            #pragma unroll
            for (int j = 0; j < 4; j++) s[i][j] = 0.f;

        #pragma unroll 8
        for (int d = 0; d < 128; d++) {
            float qv[8], kv[4];
            #pragma unroll
            for (int i = 0; i < 8; i++) qv[i] = Qs[(ty + 16 * i) * QP + d];
            #pragma unroll
            for (int j = 0; j < 4; j++) kv[j] = Kt[d * KP + tx + 16 * j];
            #pragma unroll
            for (int i = 0; i < 8; i++)
                #pragma unroll
                for (int j = 0; j < 4; j++)
                    s[i][j] = fmaf(qv[i], kv[j], s[i][j]);
        }

        // ---- causal mask + online softmax ----
        #pragma unroll
        for (int i = 0; i < 8; i++) {
            const int qrow = qt * 128 + ty + 16 * i;
            #pragma unroll
            for (int j = 0; j < 4; j++) {
                const int kcol = jt * 64 + tx + 16 * j;
                if (kcol > qrow) s[i][j] = -3.0e38f;
            }
            float mx = fmaxf(fmaxf(s[i][0], s[i][1]), fmaxf(s[i][2], s[i][3]));
            #pragma unroll
            for (int mm = 1; mm < 16; mm <<= 1)
                mx = fmaxf(mx, __shfl_xor_sync(0xffffffffu, mx, mm));
            const float mnew = fmaxf(m[i], mx);
            const float alpha = __expf(m[i] - mnew);
            float rs = 0.f;
            #pragma unroll
            for (int j = 0; j < 4; j++) {
                float p = __expf(s[i][j] - mnew);
                s[i][j] = p;
                rs += p;
            }
            #pragma unroll
            for (int mm = 1; mm < 16; mm <<= 1)
                rs += __shfl_xor_sync(0xffffffffu, rs, mm);
            l[i] = l[i] * alpha + rs;
            m[i] = mnew;
            #pragma unroll
            for (int j = 0; j < 8; j++) o[i][j] *= alpha;
            #pragma unroll
            for (int j = 0; j < 4; j++)
                Ps[(ty + 16 * i) * PP + tx + 16 * j] = s[i][j];
        }
        __syncthreads();

        // ---- O += P @ V : per thread 8 rows x 8 cols ----
        #pragma unroll 8
        for (int c = 0; c < 64; c++) {
            float pv[8], vv[8];
            #pragma unroll
            for (int i = 0; i < 8; i++) pv[i] = Ps[(ty + 16 * i) * PP + c];
            #pragma unroll
            for (int j = 0; j < 8; j++) vv[j] = Vs[c * VP + tx + 16 * j];
            #pragma unroll
            for (int i = 0; i < 8; i++)
                #pragma unroll
                for (int j = 0; j < 8; j++)
                    o[i][j] = fmaf(pv[i], vv[j], o[i][j]);
        }
        __syncthreads();
    }

    // ---- write context ----
    #pragma unroll
    for (int i = 0; i < 8; i++) {
        const float inv = 1.0f / l[i];
        const int row = qt * 128 + ty + 16 * i;
        float* dst = CTX + ((size_t)(b * SEQ + row)) * QCOLS + h * HD;
        #pragma unroll
        for (int j = 0; j < 8; j++)
            dst[tx + 16 * j] = o[i][j] * inv;
    }
}

// ============================================================================
// Launch
// ============================================================================
extern "C" void kernel_launch(void* const* d_in, const int* in_sizes, int n_in,
                              void* d_out, int out_size)
{
    const float* hidden = (const float*)d_in[0];
    // d_in[1] = attention_mask (causal tril) — recomputed analytically, unused
    const int*   pos    = (const int*)  d_in[2];
    const float* Wq     = (const float*)d_in[3];
    const float* Wk     = (const float*)d_in[4];
    const float* Wv     = (const float*)d_in[5];
    const float* Wo     = (const float*)d_in[6];
    const float* qw     = (const float*)d_in[7];
    const float* kw     = (const float*)d_in[8];
    float* out = (float*)d_out;

    float *Qp, *Kp, *Vp, *Cp;
    cudaGetSymbolAddress((void**)&Qp, g_Q);
    cudaGetSymbolAddress((void**)&Kp, g_K);
    cudaGetSymbolAddress((void**)&Vp, g_V);
    cudaGetSymbolAddress((void**)&Cp, g_CTX);

    // QKV projections
    sgemm_kernel<<<dim3(QCOLS / 128, NTOK / 128), 256>>>(hidden, Wq, Qp, NTOK, QCOLS, HID);
    sgemm_kernel<<<dim3(KVCOLS / 128, NTOK / 128), 256>>>(hidden, Wk, Kp, NTOK, KVCOLS, HID);
    sgemm_kernel<<<dim3(KVCOLS / 128, NTOK / 128), 256>>>(hidden, Wv, Vp, NTOK, KVCOLS, HID);

    // RMSNorm + RoPE
    rmsrope_kernel<<<NTOK * NH, 128>>>(Qp, qw, pos, NH);
    rmsrope_kernel<<<NTOK * NKV, 128>>>(Kp, kw, pos, NKV);

    // Flash attention
    cudaFuncSetAttribute(attn_kernel, cudaFuncAttributeMaxDynamicSharedMemorySize, ATTN_SMEM);
    attn_kernel<<<dim3(SEQ / 128, NH, BATCH), 256, ATTN_SMEM>>>(Qp, Kp, Vp, Cp);

    // Output projection
    sgemm_kernel<<<dim3(HID / 128, NTOK / 128), 256>>>(Cp, Wo, out, NTOK, HID, QCOLS);
}

// round 2
// speedup vs baseline: 1.2853x; 1.2853x over previous
#include <cuda_runtime.h>
#include <cuda_bf16.h>
#include <math.h>
#include <stdint.h>

// Problem constants
#define BATCH 2
#define SEQ   2048
#define HID   2048
#define NH    32
#define NKV   4
#define HD    128
#define NTOK  (BATCH*SEQ)          // 4096
#define QCOLS (NH*HD)              // 4096
#define KVCOLS (NKV*HD)            // 512

// -------- scratch (device globals: no runtime allocation allowed) --------
__device__ float g_Q[(size_t)NTOK * QCOLS];    // 64 MiB
__device__ float g_K[(size_t)NTOK * KVCOLS];   // 8 MiB
__device__ float g_V[(size_t)NTOK * KVCOLS];   // 8 MiB
__device__ float g_CTX[(size_t)NTOK * QCOLS];  // 64 MiB

// ============================================================================
// PTX helpers
// ============================================================================
__device__ __forceinline__ uint32_t smem_u32(const void* p) {
    return (uint32_t)__cvta_generic_to_shared(p);
}
__device__ __forceinline__ void ldmatrix_x4(uint32_t* r, uint32_t addr) {
    asm volatile("ldmatrix.sync.aligned.m8n8.x4.shared.b16 {%0,%1,%2,%3}, [%4];"
                 : "=r"(r[0]), "=r"(r[1]), "=r"(r[2]), "=r"(r[3]) : "r"(addr));
}
__device__ __forceinline__ void ldmatrix_x2_trans(uint32_t* r, uint32_t addr) {
    asm volatile("ldmatrix.sync.aligned.m8n8.x2.trans.shared.b16 {%0,%1}, [%2];"
                 : "=r"(r[0]), "=r"(r[1]) : "r"(addr));
}
__device__ __forceinline__ void mma_bf16(float* d, const uint32_t* a, const uint32_t* b) {
    asm volatile("mma.sync.aligned.m16n8k16.row.col.f32.bf16.bf16.f32 "
                 "{%0,%1,%2,%3}, {%4,%5,%6,%7}, {%8,%9}, {%0,%1,%2,%3};"
                 : "+f"(d[0]), "+f"(d[1]), "+f"(d[2]), "+f"(d[3])
                 : "r"(a[0]), "r"(a[1]), "r"(a[2]), "r"(a[3]),
                   "r"(b[0]), "r"(b[1]));
}
__device__ __forceinline__ void split2(float x, __nv_bfloat16& h, __nv_bfloat16& l) {
    h = __float2bfloat16_rn(x);
    l = __float2bfloat16_rn(x - __bfloat162float(h));
}

// ============================================================================
// GEMM via split-bf16 tensor cores: C[M,N] = A[M,K] @ B[K,N] (fp32 in/out).
// Each fp32 x = hi + lo (bf16 each); C ~= Ah*Bh + Ah*Bl + Al*Bh.
// 128x128 block tile, BK=32, 256 threads (8 warps: 4x2 of 32x64).
// ============================================================================
__global__ __launch_bounds__(256, 2)
void gemm_bf16x3(const float* __restrict__ A, const float* __restrict__ Bm,
                 float* __restrict__ C, int M, int N, int K)
{
    __shared__ __nv_bfloat16 Ah[128][40];
    __shared__ __nv_bfloat16 Al[128][40];
    __shared__ __nv_bfloat16 Bh[32][136];
    __shared__ __nv_bfloat16 Bl[32][136];

    const int tid  = threadIdx.x;
    const int warp = tid >> 5;
    const int lane = tid & 31;
    const int wm = (warp >> 1) * 32;     // warp M offset: 0..96
    const int wn = (warp & 1) * 64;      // warp N offset: 0,64
    const int bx = blockIdx.x * 128;     // N block offset
    const int by = blockIdx.y * 128;     // M block offset

    // loader mapping
    const int ar = tid >> 1;             // A row 0..127
    const int ac = (tid & 1) * 16;       // A col base 0/16
    const int br = tid >> 3;             // B row 0..31
    const int bc = (tid & 7) * 16;       // B col base 0..112

    float acc[2][8][4];
    #pragma unroll
    for (int mi = 0; mi < 2; mi++)
        #pragma unroll
        for (int ni = 0; ni < 8; ni++)
            #pragma unroll
            for (int e = 0; e < 4; e++) acc[mi][ni][e] = 0.f;

    const float* Aptr = A + (size_t)(by + ar) * K;
    const float* Bptr = Bm + bx;

    for (int k0 = 0; k0 < K; k0 += 32) {
        // ---- fill smem with split-bf16 tiles ----
        #pragma unroll
        for (int u = 0; u < 4; u++) {
            float4 v = *(const float4*)(Aptr + k0 + ac + 4 * u);
            split2(v.x, Ah[ar][ac + 4*u + 0], Al[ar][ac + 4*u + 0]);
            split2(v.y, Ah[ar][ac + 4*u + 1], Al[ar][ac + 4*u + 1]);
            split2(v.z, Ah[ar][ac + 4*u + 2], Al[ar][ac + 4*u + 2]);
            split2(v.w, Ah[ar][ac + 4*u + 3], Al[ar][ac + 4*u + 3]);
        }
        #pragma unroll
        for (int u = 0; u < 4; u++) {
            float4 v = *(const float4*)(Bptr + (size_t)(k0 + br) * N + bc + 4 * u);
            split2(v.x, Bh[br][bc + 4*u + 0], Bl[br][bc + 4*u + 0]);
            split2(v.y, Bh[br][bc + 4*u + 1], Bl[br][bc + 4*u + 1]);
            split2(v.z, Bh[br][bc + 4*u + 2], Bl[br][bc + 4*u + 2]);
            split2(v.w, Bh[br][bc + 4*u + 3], Bl[br][bc + 4*u + 3]);
        }
        __syncthreads();

        // ---- tensor-core compute ----
        #pragma unroll
        for (int kk = 0; kk < 32; kk += 16) {
            uint32_t ah[2][4], al[2][4];
            #pragma unroll
            for (int mi = 0; mi < 2; mi++) {
                const int row = wm + mi * 16 + (lane & 15);
                const int col = kk + ((lane >> 4) << 3);
                ldmatrix_x4(ah[mi], smem_u32(&Ah[row][col]));
                ldmatrix_x4(al[mi], smem_u32(&Al[row][col]));
            }
            #pragma unroll
            for (int ni = 0; ni < 8; ni++) {
                uint32_t bh[2], bl[2];
                const int krow = kk + (lane & 15);
                const int ncol = wn + ni * 8;
                ldmatrix_x2_trans(bh, smem_u32(&Bh[krow][ncol]));
                ldmatrix_x2_trans(bl, smem_u32(&Bl[krow][ncol]));
                #pragma unroll
                for (int mi = 0; mi < 2; mi++) {
                    mma_bf16(acc[mi][ni], ah[mi], bh);
                    mma_bf16(acc[mi][ni], ah[mi], bl);
                    mma_bf16(acc[mi][ni], al[mi], bh);
                }
            }
        }
        __syncthreads();
    }

    // ---- epilogue ----
    const int g = lane >> 2;
    const int t = lane & 3;
    #pragma unroll
    for (int mi = 0; mi < 2; mi++) {
        #pragma unroll
        for (int ni = 0; ni < 8; ni++) {
            const size_t row0 = (size_t)(by + wm + mi * 16 + g);
            const int col = bx + wn + ni * 8 + 2 * t;
            *(float2*)(C + row0 * N + col)       = make_float2(acc[mi][ni][0], acc[mi][ni][1]);
            *(float2*)(C + (row0 + 8) * N + col) = make_float2(acc[mi][ni][2], acc[mi][ni][3]);
        }
    }
}

// ============================================================================
// RMSNorm + RoPE, one block of 128 threads per (token, head). In-place.
// ============================================================================
__global__ __launch_bounds__(128)
void rmsrope_kernel(float* __restrict__ X, const float* __restrict__ w,
                    const int* __restrict__ pos, int nheads)
{
    const int blk = blockIdx.x;
    const int token = blk / nheads;
    const int h     = blk % nheads;
    float* x = X + (size_t)token * (nheads * HD) + h * HD;

    const int i = threadIdx.x;
    float v = x[i];

    float ss = v * v;
    #pragma unroll
    for (int m = 16; m; m >>= 1) ss += __shfl_xor_sync(0xffffffffu, ss, m);
    __shared__ float wsum[4];
    if ((i & 31) == 0) wsum[i >> 5] = ss;
    __syncthreads();
    float tot = wsum[0] + wsum[1] + wsum[2] + wsum[3];
    float inv = rsqrtf(tot * (1.0f / 128.0f) + 1e-6f);

    __shared__ float xs[128];
    xs[i] = v * inv * w[i];
    __syncthreads();

    const int p = pos[token];
    const int j = i & 63;
    float invf = (float)pow(1.0e6, -(double)j / 64.0);
    float f = (float)p * invf;
    float c, s;
    sincosf(f, &s, &c);
    float xi = xs[i];
    float partner = (i < 64) ? -xs[i + 64] : xs[i - 64];
    x[i] = xi * c + partner * s;
}

// ============================================================================
// Flash attention, fp32, causal. Br=128, Bc=64, 256 threads.
// ============================================================================
#define QP 132
#define KP 68
#define VP 132
#define PP 68
#define ATTN_SMEM ((128*QP + 128*KP + 64*VP + 128*PP) * 4)

__global__ __launch_bounds__(256, 1)
void attn_kernel(const float* __restrict__ Q, const float* __restrict__ K,
                 const float* __restrict__ V, float* __restrict__ CTX)
{
    extern __shared__ float sm[];
    float* Qs = sm;                    // [128][QP]
    float* Kt = Qs + 128 * QP;         // [128][KP] transposed: Kt[d][c]
    float* Vs = Kt + 128 * KP;         // [64][VP]
    float* Ps = Vs + 64 * VP;          // [128][PP]

    const int qt = gridDim.x - 1 - blockIdx.x;
    const int h  = blockIdx.y;
    const int b  = blockIdx.z;
    const int hk = h >> 3;

    const int tid = threadIdx.x;
    const int ty = tid >> 4;
    const int tx = tid & 15;

    const float scale = 0.08838834764831845f;

    {
        const int r  = tid >> 1;
        const int d0 = (tid & 1) * 64;
        const float* src = Q + ((size_t)(b * SEQ + qt * 128 + r)) * QCOLS + h * HD + d0;
        float* dst = Qs + r * QP + d0;
        #pragma unroll
        for (int u = 0; u < 16; u++) {
            float4 v = *(const float4*)(src + 4 * u);
            dst[4 * u + 0] = v.x * scale;
            dst[4 * u + 1] = v.y * scale;
            dst[4 * u + 2] = v.z * scale;
            dst[4 * u + 3] = v.w * scale;
        }
    }

    float o[8][8];
    float m[8], l[8];
    #pragma unroll
    for (int i = 0; i < 8; i++) {
        m[i] = -3.0e38f; l[i] = 0.f;
        #pragma unroll
        for (int j = 0; j < 8; j++) o[i][j] = 0.f;
    }

    const int ntiles = 2 * qt + 2;
    for (int jt = 0; jt < ntiles; jt++) {
        {
            const int c  = tid >> 2;
            const int d0 = (tid & 3) * 32;
            const size_t tok = (size_t)(b * SEQ + jt * 64 + c);
            const float* ksrc = K + tok * KVCOLS + hk * HD + d0;
            const float* vsrc = V + tok * KVCOLS + hk * HD + d0;
            float* vdst = Vs + c * VP + d0;
            #pragma unroll
            for (int u = 0; u < 8; u++) {
                float4 kv = *(const float4*)(ksrc + 4 * u);
                int d = d0 + 4 * u;
                Kt[(d + 0) * KP + c] = kv.x;
                Kt[(d + 1) * KP + c] = kv.y;
                Kt[(d + 2) * KP + c] = kv.z;
                Kt[(d + 3) * KP + c] = kv.w;
                *(float4*)(vdst + 4 * u) = *(const float4*)(vsrc + 4 * u);
            }
        }
        __syncthreads();

        float s[8][4];
        #pragma unroll
        for (int i = 0; i < 8; i++)
            #pragma unroll
            for (int j = 0; j < 4; j++) s[i][j] = 0.f;

        #pragma unroll 8
        for (int d = 0; d < 128; d++) {
            float qv[8], kv[4];
            #pragma unroll
            for (int i = 0; i < 8; i++) qv[i] = Qs[(ty + 16 * i) * QP + d];
            #pragma unroll
            for (int j = 0; j < 4; j++) kv[j] = Kt[d * KP + tx + 16 * j];
            #pragma unroll
            for (int i = 0; i < 8; i++)
                #pragma unroll
                for (int j = 0; j < 4; j++)
                    s[i][j] = fmaf(qv[i], kv[j], s[i][j]);
        }

        #pragma unroll
        for (int i = 0; i < 8; i++) {
            const int qrow = qt * 128 + ty + 16 * i;
            #pragma unroll
            for (int j = 0; j < 4; j++) {
                const int kcol = jt * 64 + tx + 16 * j;
                if (kcol > qrow) s[i][j] = -3.0e38f;
            }
            float mx = fmaxf(fmaxf(s[i][0], s[i][1]), fmaxf(s[i][2], s[i][3]));
            #pragma unroll
            for (int mm = 1; mm < 16; mm <<= 1)
                mx = fmaxf(mx, __shfl_xor_sync(0xffffffffu, mx, mm));
            const float mnew = fmaxf(m[i], mx);
            const float alpha = __expf(m[i] - mnew);
            float rs = 0.f;
            #pragma unroll
            for (int j = 0; j < 4; j++) {
                float p = __expf(s[i][j] - mnew);
                s[i][j] = p;
                rs += p;
            }
            #pragma unroll
            for (int mm = 1; mm < 16; mm <<= 1)
                rs += __shfl_xor_sync(0xffffffffu, rs, mm);
            l[i] = l[i] * alpha + rs;
            m[i] = mnew;
            #pragma unroll
            for (int j = 0; j < 8; j++) o[i][j] *= alpha;
            #pragma unroll
            for (int j = 0; j < 4; j++)
                Ps[(ty + 16 * i) * PP + tx + 16 * j] = s[i][j];
        }
        __syncthreads();

        #pragma unroll 8
        for (int c = 0; c < 64; c++) {
            float pv[8], vv[8];
            #pragma unroll
            for (int i = 0; i < 8; i++) pv[i] = Ps[(ty + 16 * i) * PP + c];
            #pragma unroll
            for (int j = 0; j < 8; j++) vv[j] = Vs[c * VP + tx + 16 * j];
            #pragma unroll
            for (int i = 0; i < 8; i++)
                #pragma unroll
                for (int j = 0; j < 8; j++)
                    o[i][j] = fmaf(pv[i], vv[j], o[i][j]);
        }
        __syncthreads();
    }

    #pragma unroll
    for (int i = 0; i < 8; i++) {
        const float inv = 1.0f / l[i];
        const int row = qt * 128 + ty + 16 * i;
        float* dst = CTX + ((size_t)(b * SEQ + row)) * QCOLS + h * HD;
        #pragma unroll
        for (int j = 0; j < 8; j++)
            dst[tx + 16 * j] = o[i][j] * inv;
    }
}

// ============================================================================
// Launch
// ============================================================================
extern "C" void kernel_launch(void* const* d_in, const int* in_sizes, int n_in,
                              void* d_out, int out_size)
{
    const float* hidden = (const float*)d_in[0];
    const int*   pos    = (const int*)  d_in[2];
    const float* Wq     = (const float*)d_in[3];
    const float* Wk     = (const float*)d_in[4];
    const float* Wv     = (const float*)d_in[5];
    const float* Wo     = (const float*)d_in[6];
    const float* qw     = (const float*)d_in[7];
    const float* kw     = (const float*)d_in[8];
    float* out = (float*)d_out;

    float *Qp, *Kp, *Vp, *Cp;
    cudaGetSymbolAddress((void**)&Qp, g_Q);
    cudaGetSymbolAddress((void**)&Kp, g_K);
    cudaGetSymbolAddress((void**)&Vp, g_V);
    cudaGetSymbolAddress((void**)&Cp, g_CTX);

    // QKV projections (tensor-core split-bf16)
    gemm_bf16x3<<<dim3(QCOLS / 128, NTOK / 128), 256>>>(hidden, Wq, Qp, NTOK, QCOLS, HID);
    gemm_bf16x3<<<dim3(KVCOLS / 128, NTOK / 128), 256>>>(hidden, Wk, Kp, NTOK, KVCOLS, HID);
    gemm_bf16x3<<<dim3(KVCOLS / 128, NTOK / 128), 256>>>(hidden, Wv, Vp, NTOK, KVCOLS, HID);

    // RMSNorm + RoPE
    rmsrope_kernel<<<NTOK * NH, 128>>>(Qp, qw, pos, NH);
    rmsrope_kernel<<<NTOK * NKV, 128>>>(Kp, kw, pos, NKV);

    // Flash attention (fp32 — next optimization target)
    cudaFuncSetAttribute(attn_kernel, cudaFuncAttributeMaxDynamicSharedMemorySize, ATTN_SMEM);
    attn_kernel<<<dim3(SEQ / 128, NH, BATCH), 256, ATTN_SMEM>>>(Qp, Kp, Vp, Cp);

    // Output projection
    gemm_bf16x3<<<dim3(HID / 128, NTOK / 128), 256>>>(Cp, Wo, out, NTOK, HID, QCOLS);
}

// round 3
// speedup vs baseline: 1.5157x; 1.1793x over previous
#include <cuda_runtime.h>
#include <cuda_bf16.h>
#include <math.h>
#include <stdint.h>

// Problem constants
#define BATCH 2
#define SEQ   2048
#define HID   2048
#define NH    32
#define NKV   4
#define HD    128
#define NTOK  (BATCH*SEQ)          // 4096
#define QCOLS (NH*HD)              // 4096
#define KVCOLS (NKV*HD)            // 512

// -------- scratch (device globals: no runtime allocation allowed) --------
__device__ float g_Q[(size_t)NTOK * QCOLS];    // 64 MiB
__device__ float g_K[(size_t)NTOK * KVCOLS];   // 8 MiB
__device__ float g_V[(size_t)NTOK * KVCOLS];   // 8 MiB
__device__ float g_CTX[(size_t)NTOK * QCOLS];  // 64 MiB

// ============================================================================
// PTX helpers
// ============================================================================
__device__ __forceinline__ uint32_t smem_u32(const void* p) {
    return (uint32_t)__cvta_generic_to_shared(p);
}
__device__ __forceinline__ void ldmatrix_x4(uint32_t* r, uint32_t addr) {
    asm volatile("ldmatrix.sync.aligned.m8n8.x4.shared.b16 {%0,%1,%2,%3}, [%4];"
                 : "=r"(r[0]), "=r"(r[1]), "=r"(r[2]), "=r"(r[3]) : "r"(addr));
}
__device__ __forceinline__ void ldmatrix_x2_trans(uint32_t* r, uint32_t addr) {
    asm volatile("ldmatrix.sync.aligned.m8n8.x2.trans.shared.b16 {%0,%1}, [%2];"
                 : "=r"(r[0]), "=r"(r[1]) : "r"(addr));
}
__device__ __forceinline__ void mma_bf16(float* d, const uint32_t* a, const uint32_t* b) {
    asm volatile("mma.sync.aligned.m16n8k16.row.col.f32.bf16.bf16.f32 "
                 "{%0,%1,%2,%3}, {%4,%5,%6,%7}, {%8,%9}, {%0,%1,%2,%3};"
                 : "+f"(d[0]), "+f"(d[1]), "+f"(d[2]), "+f"(d[3])
                 : "r"(a[0]), "r"(a[1]), "r"(a[2]), "r"(a[3]),
                   "r"(b[0]), "r"(b[1]));
}
__device__ __forceinline__ void split2(float x, __nv_bfloat16& h, __nv_bfloat16& l) {
    h = __float2bfloat16_rn(x);
    l = __float2bfloat16_rn(x - __bfloat162float(h));
}
__device__ __forceinline__ uint32_t pack_bf16x2(float lo, float hi) {
    __nv_bfloat162 r = __floats2bfloat162_rn(lo, hi);
    return *(uint32_t*)&r;
}

// ============================================================================
// GEMM via split-bf16 tensor cores: C[M,N] = A[M,K] @ B[K,N] (fp32 in/out).
// ============================================================================
__global__ __launch_bounds__(256, 2)
void gemm_bf16x3(const float* __restrict__ A, const float* __restrict__ Bm,
                 float* __restrict__ C, int M, int N, int K)
{
    __shared__ __nv_bfloat16 Ah[128][40];
    __shared__ __nv_bfloat16 Al[128][40];
    __shared__ __nv_bfloat16 Bh[32][136];
    __shared__ __nv_bfloat16 Bl[32][136];

    const int tid  = threadIdx.x;
    const int warp = tid >> 5;
    const int lane = tid & 31;
    const int wm = (warp >> 1) * 32;
    const int wn = (warp & 1) * 64;
    const int bx = blockIdx.x * 128;
    const int by = blockIdx.y * 128;

    const int ar = tid >> 1;
    const int ac = (tid & 1) * 16;
    const int br = tid >> 3;
    const int bc = (tid & 7) * 16;

    float acc[2][8][4];
    #pragma unroll
    for (int mi = 0; mi < 2; mi++)
        #pragma unroll
        for (int ni = 0; ni < 8; ni++)
            #pragma unroll
            for (int e = 0; e < 4; e++) acc[mi][ni][e] = 0.f;

    const float* Aptr = A + (size_t)(by + ar) * K;
    const float* Bptr = Bm + bx;

    for (int k0 = 0; k0 < K; k0 += 32) {
        #pragma unroll
        for (int u = 0; u < 4; u++) {
            float4 v = *(const float4*)(Aptr + k0 + ac + 4 * u);
            split2(v.x, Ah[ar][ac + 4*u + 0], Al[ar][ac + 4*u + 0]);
            split2(v.y, Ah[ar][ac + 4*u + 1], Al[ar][ac + 4*u + 1]);
            split2(v.z, Ah[ar][ac + 4*u + 2], Al[ar][ac + 4*u + 2]);
            split2(v.w, Ah[ar][ac + 4*u + 3], Al[ar][ac + 4*u + 3]);
        }
        #pragma unroll
        for (int u = 0; u < 4; u++) {
            float4 v = *(const float4*)(Bptr + (size_t)(k0 + br) * N + bc + 4 * u);
            split2(v.x, Bh[br][bc + 4*u + 0], Bl[br][bc + 4*u + 0]);
            split2(v.y, Bh[br][bc + 4*u + 1], Bl[br][bc + 4*u + 1]);
            split2(v.z, Bh[br][bc + 4*u + 2], Bl[br][bc + 4*u + 2]);
            split2(v.w, Bh[br][bc + 4*u + 3], Bl[br][bc + 4*u + 3]);
        }
        __syncthreads();

        #pragma unroll
        for (int kk = 0; kk < 32; kk += 16) {
            uint32_t ah[2][4], al[2][4];
            #pragma unroll
            for (int mi = 0; mi < 2; mi++) {
                const int row = wm + mi * 16 + (lane & 15);
                const int col = kk + ((lane >> 4) << 3);
                ldmatrix_x4(ah[mi], smem_u32(&Ah[row][col]));
                ldmatrix_x4(al[mi], smem_u32(&Al[row][col]));
            }
            #pragma unroll
            for (int ni = 0; ni < 8; ni++) {
                uint32_t bh[2], bl[2];
                const int krow = kk + (lane & 15);
                const int ncol = wn + ni * 8;
                ldmatrix_x2_trans(bh, smem_u32(&Bh[krow][ncol]));
                ldmatrix_x2_trans(bl, smem_u32(&Bl[krow][ncol]));
                #pragma unroll
                for (int mi = 0; mi < 2; mi++) {
                    mma_bf16(acc[mi][ni], ah[mi], bh);
                    mma_bf16(acc[mi][ni], ah[mi], bl);
                    mma_bf16(acc[mi][ni], al[mi], bh);
                }
            }
        }
        __syncthreads();
    }

    const int g = lane >> 2;
    const int t = lane & 3;
    #pragma unroll
    for (int mi = 0; mi < 2; mi++) {
        #pragma unroll
        for (int ni = 0; ni < 8; ni++) {
            const size_t row0 = (size_t)(by + wm + mi * 16 + g);
            const int col = bx + wn + ni * 8 + 2 * t;
            *(float2*)(C + row0 * N + col)       = make_float2(acc[mi][ni][0], acc[mi][ni][1]);
            *(float2*)(C + (row0 + 8) * N + col) = make_float2(acc[mi][ni][2], acc[mi][ni][3]);
        }
    }
}

// ============================================================================
// RMSNorm + RoPE, one block of 128 threads per (token, head). In-place.
// ============================================================================
__global__ __launch_bounds__(128)
void rmsrope_kernel(float* __restrict__ X, const float* __restrict__ w,
                    const int* __restrict__ pos, int nheads)
{
    const int blk = blockIdx.x;
    const int token = blk / nheads;
    const int h     = blk % nheads;
    float* x = X + (size_t)token * (nheads * HD) + h * HD;

    const int i = threadIdx.x;
    float v = x[i];

    float ss = v * v;
    #pragma unroll
    for (int m = 16; m; m >>= 1) ss += __shfl_xor_sync(0xffffffffu, ss, m);
    __shared__ float wsum[4];
    if ((i & 31) == 0) wsum[i >> 5] = ss;
    __syncthreads();
    float tot = wsum[0] + wsum[1] + wsum[2] + wsum[3];
    float inv = rsqrtf(tot * (1.0f / 128.0f) + 1e-6f);

    __shared__ float xs[128];
    xs[i] = v * inv * w[i];
    __syncthreads();

    const int p = pos[token];
    const int j = i & 63;
    float invf = (float)pow(1.0e6, -(double)j / 64.0);
    float f = (float)p * invf;
    float c, s;
    sincosf(f, &s, &c);
    float xi = xs[i];
    float partner = (i < 64) ? -xs[i + 64] : xs[i - 64];
    x[i] = xi * c + partner * s;
}

// ============================================================================
// Tensor-core flash attention (split-bf16, 3-term), causal.
// Br=128 (8 warps x 16 rows), Bc=64, 256 threads. grid=(SEQ/128, NH, B).
// ============================================================================
#define QSTR 136
#define KSTR 72
#define VSTR 136
#define ATTN_SMEM ((2*128*QSTR + 2*128*KSTR + 2*64*VSTR) * 2)

__global__ __launch_bounds__(256, 1)
void attn_tc_kernel(const float* __restrict__ Q, const float* __restrict__ K,
                    const float* __restrict__ V, float* __restrict__ CTX)
{
    extern __shared__ __nv_bfloat16 smb[];
    __nv_bfloat16* Qh  = smb;
    __nv_bfloat16* Ql  = Qh  + 128 * QSTR;
    __nv_bfloat16* Kth = Ql  + 128 * QSTR;   // [d][token]
    __nv_bfloat16* Ktl = Kth + 128 * KSTR;
    __nv_bfloat16* Vh  = Ktl + 128 * KSTR;   // [token][d]
    __nv_bfloat16* Vl  = Vh  + 64 * VSTR;

    const int qt = gridDim.x - 1 - blockIdx.x;
    const int h  = blockIdx.y;
    const int b  = blockIdx.z;
    const int hk = h >> 3;

    const int tid  = threadIdx.x;
    const int warp = tid >> 5;
    const int lane = tid & 31;
    const int g  = lane >> 2;
    const int t4 = lane & 3;

    const float scale = 0.08838834764831845f;   // 1/sqrt(128)

    // ---- load + split Q tile (128x128), pre-scaled ----
    {
        const int r  = tid >> 1;
        const int c0 = (tid & 1) * 64;
        const float* src = Q + ((size_t)(b * SEQ + qt * 128 + r)) * QCOLS + h * HD + c0;
        #pragma unroll
        for (int u = 0; u < 16; u++) {
            float4 v = *(const float4*)(src + 4 * u);
            const int c = c0 + 4 * u;
            split2(v.x * scale, Qh[r*QSTR + c+0], Ql[r*QSTR + c+0]);
            split2(v.y * scale, Qh[r*QSTR + c+1], Ql[r*QSTR + c+1]);
            split2(v.z * scale, Qh[r*QSTR + c+2], Ql[r*QSTR + c+2]);
            split2(v.w * scale, Qh[r*QSTR + c+3], Ql[r*QSTR + c+3]);
        }
    }

    float oacc[16][4];
    #pragma unroll
    for (int nt = 0; nt < 16; nt++)
        #pragma unroll
        for (int e = 0; e < 4; e++) oacc[nt][e] = 0.f;
    float mrow0 = -1e30f, mrow1 = -1e30f, lrow0 = 0.f, lrow1 = 0.f;

    const int qrow0 = qt * 128 + warp * 16 + g;
    const int qrow1 = qrow0 + 8;
    const int warp_maxrow = qt * 128 + warp * 16 + 15;

    // precomputed ldmatrix addresses
    const uint32_t qh_base  = smem_u32(&Qh [(warp*16 + (lane & 15)) * QSTR + ((lane >> 4) << 3)]);
    const uint32_t ql_base  = smem_u32(&Ql [(warp*16 + (lane & 15)) * QSTR + ((lane >> 4) << 3)]);
    const uint32_t kth_base = smem_u32(&Kth[(lane & 15) * KSTR]);
    const uint32_t ktl_base = smem_u32(&Ktl[(lane & 15) * KSTR]);
    const uint32_t vh_base  = smem_u32(&Vh [(lane & 15) * VSTR]);
    const uint32_t vl_base  = smem_u32(&Vl [(lane & 15) * VSTR]);

    const int ntiles = 2 * qt + 2;
    for (int jt = 0; jt < ntiles; jt++) {
        __syncthreads();   // previous iteration's smem reads done (also covers Q fill)
        // ---- load + split K (transposed) and V tiles (64 tokens x 128 d) ----
        {
            const int c  = tid >> 2;
            const int d0 = (tid & 3) * 32;
            const size_t tok = (size_t)(b * SEQ + jt * 64 + c);
            const float* ksrc = K + tok * KVCOLS + hk * HD + d0;
            const float* vsrc = V + tok * KVCOLS + hk * HD + d0;
            #pragma unroll
            for (int u = 0; u < 8; u++) {
                float4 kv = *(const float4*)(ksrc + 4 * u);
                const int d = d0 + 4 * u;
                split2(kv.x, Kth[(d+0)*KSTR + c], Ktl[(d+0)*KSTR + c]);
                split2(kv.y, Kth[(d+1)*KSTR + c], Ktl[(d+1)*KSTR + c]);
                split2(kv.z, Kth[(d+2)*KSTR + c], Ktl[(d+2)*KSTR + c]);
                split2(kv.w, Kth[(d+3)*KSTR + c], Ktl[(d+3)*KSTR + c]);
                float4 vv = *(const float4*)(vsrc + 4 * u);
                split2(vv.x, Vh[c*VSTR + d+0], Vl[c*VSTR + d+0]);
                split2(vv.y, Vh[c*VSTR + d+1], Vl[c*VSTR + d+1]);
                split2(vv.z, Vh[c*VSTR + d+2], Vl[c*VSTR + d+2]);
                split2(vv.w, Vh[c*VSTR + d+3], Vl[c*VSTR + d+3]);
            }
        }
        __syncthreads();

        // per-warp skip of fully-masked tiles (warp-uniform branch)
        if (jt * 64 > warp_maxrow) continue;

        // ---- S = Q @ Kt : 8 n-tiles of m16n8, k=128 ----
        float sacc[8][4];
        #pragma unroll
        for (int nt = 0; nt < 8; nt++)
            #pragma unroll
            for (int e = 0; e < 4; e++) sacc[nt][e] = 0.f;

        #pragma unroll
        for (int kk = 0; kk < 8; kk++) {
            uint32_t ah[4], al[4];
            ldmatrix_x4(ah, qh_base + kk * 16 * sizeof(__nv_bfloat16));
            ldmatrix_x4(al, ql_base + kk * 16 * sizeof(__nv_bfloat16));
            #pragma unroll
            for (int nt = 0; nt < 8; nt++) {
                uint32_t bh[2], bl[2];
                const uint32_t off = (kk * 16 * KSTR + nt * 8) * sizeof(__nv_bfloat16);
                ldmatrix_x2_trans(bh, kth_base + off);
                ldmatrix_x2_trans(bl, ktl_base + off);
                mma_bf16(sacc[nt], ah, bh);
                mma_bf16(sacc[nt], ah, bl);
                mma_bf16(sacc[nt], al, bh);
            }
        }

        // ---- causal mask + online softmax on fragments ----
        float mx0 = -1e30f, mx1 = -1e30f;
        #pragma unroll
        for (int nt = 0; nt < 8; nt++) {
            const int col = jt * 64 + nt * 8 + 2 * t4;
            if (col     > qrow0) sacc[nt][0] = -1e30f;
            if (col + 1 > qrow0) sacc[nt][1] = -1e30f;
            if (col     > qrow1) sacc[nt][2] = -1e30f;
            if (col + 1 > qrow1) sacc[nt][3] = -1e30f;
            mx0 = fmaxf(mx0, fmaxf(sacc[nt][0], sacc[nt][1]));
            mx1 = fmaxf(mx1, fmaxf(sacc[nt][2], sacc[nt][3]));
        }
        mx0 = fmaxf(mx0, __shfl_xor_sync(0xffffffffu, mx0, 1));
        mx0 = fmaxf(mx0, __shfl_xor_sync(0xffffffffu, mx0, 2));
        mx1 = fmaxf(mx1, __shfl_xor_sync(0xffffffffu, mx1, 1));
        mx1 = fmaxf(mx1, __shfl_xor_sync(0xffffffffu, mx1, 2));

        const float mnew0 = fmaxf(mrow0, mx0);
        const float mnew1 = fmaxf(mrow1, mx1);
        const float alpha0 = __expf(mrow0 - mnew0);
        const float alpha1 = __expf(mrow1 - mnew1);

        float rs0 = 0.f, rs1 = 0.f;
        #pragma unroll
        for (int nt = 0; nt < 8; nt++) {
            sacc[nt][0] = __expf(sacc[nt][0] - mnew0);
            sacc[nt][1] = __expf(sacc[nt][1] - mnew0);
            sacc[nt][2] = __expf(sacc[nt][2] - mnew1);
            sacc[nt][3] = __expf(sacc[nt][3] - mnew1);
            rs0 += sacc[nt][0] + sacc[nt][1];
            rs1 += sacc[nt][2] + sacc[nt][3];
        }
        rs0 += __shfl_xor_sync(0xffffffffu, rs0, 1);
        rs0 += __shfl_xor_sync(0xffffffffu, rs0, 2);
        rs1 += __shfl_xor_sync(0xffffffffu, rs1, 1);
        rs1 += __shfl_xor_sync(0xffffffffu, rs1, 2);

        lrow0 = lrow0 * alpha0 + rs0;
        lrow1 = lrow1 * alpha1 + rs1;
        mrow0 = mnew0;
        mrow1 = mnew1;

        #pragma unroll
        for (int nt = 0; nt < 16; nt++) {
            oacc[nt][0] *= alpha0;
            oacc[nt][1] *= alpha0;
            oacc[nt][2] *= alpha1;
            oacc[nt][3] *= alpha1;
        }

        // ---- O += P @ V : pack P from sacc registers (FA2 identity) ----
        #pragma unroll
        for (int c = 0; c < 4; c++) {
            uint32_t ph[4], pl[4];
            {
                const float p00 = sacc[2*c][0],   p01 = sacc[2*c][1];
                const float p02 = sacc[2*c][2],   p03 = sacc[2*c][3];
                const float p10 = sacc[2*c+1][0], p11 = sacc[2*c+1][1];
                const float p12 = sacc[2*c+1][2], p13 = sacc[2*c+1][3];
                __nv_bfloat16 h00, l00, h01, l01, h02, l02, h03, l03;
                __nv_bfloat16 h10, l10, h11, l11, h12, l12, h13, l13;
                split2(p00, h00, l00); split2(p01, h01, l01);
                split2(p02, h02, l02); split2(p03, h03, l03);
                split2(p10, h10, l10); split2(p11, h11, l11);
                split2(p12, h12, l12); split2(p13, h13, l13);
                ph[0] = pack_bf16x2(__bfloat162float(h00), __bfloat162float(h01));
                ph[1] = pack_bf16x2(__bfloat162float(h02), __bfloat162float(h03));
                ph[2] = pack_bf16x2(__bfloat162float(h10), __bfloat162float(h11));
                ph[3] = pack_bf16x2(__bfloat162float(h12), __bfloat162float(h13));
                pl[0] = pack_bf16x2(__bfloat162float(l00), __bfloat162float(l01));
                pl[1] = pack_bf16x2(__bfloat162float(l02), __bfloat162float(l03));
                pl[2] = pack_bf16x2(__bfloat162float(l10), __bfloat162float(l11));
                pl[3] = pack_bf16x2(__bfloat162float(l12), __bfloat162float(l13));
            }
            #pragma unroll
            for (int nt = 0; nt < 16; nt++) {
                uint32_t vh[2], vl[2];
                const uint32_t off = (c * 16 * VSTR + nt * 8) * sizeof(__nv_bfloat16);
                ldmatrix_x2_trans(vh, vh_base + off);
                ldmatrix_x2_trans(vl, vl_base + off);
                mma_bf16(oacc[nt], ph, vh);
                mma_bf16(oacc[nt], pl, vh);
                mma_bf16(oacc[nt], ph, vl);
            }
        }
    }

    // ---- epilogue ----
    const float inv0 = 1.0f / lrow0;
    const float inv1 = 1.0f / lrow1;
    float* dst0 = CTX + ((size_t)(b * SEQ + qrow0)) * QCOLS + h * HD;
    float* dst1 = CTX + ((size_t)(b * SEQ + qrow1)) * QCOLS + h * HD;
    #pragma unroll
    for (int nt = 0; nt < 16; nt++) {
        const int col = nt * 8 + 2 * t4;
        *(float2*)(dst0 + col) = make_float2(oacc[nt][0] * inv0, oacc[nt][1] * inv0);
        *(float2*)(dst1 + col) = make_float2(oacc[nt][2] * inv1, oacc[nt][3] * inv1);
    }
}

// ============================================================================
// Launch
// ============================================================================
extern "C" void kernel_launch(void* const* d_in, const int* in_sizes, int n_in,
                              void* d_out, int out_size)
{
    const float* hidden = (const float*)d_in[0];
    const int*   pos    = (const int*)  d_in[2];
    const float* Wq     = (const float*)d_in[3];
    const float* Wk     = (const float*)d_in[4];
    const float* Wv     = (const float*)d_in[5];
    const float* Wo     = (const float*)d_in[6];
    const float* qw     = (const float*)d_in[7];
    const float* kw     = (const float*)d_in[8];
    float* out = (float*)d_out;

    float *Qp, *Kp, *Vp, *Cp;
    cudaGetSymbolAddress((void**)&Qp, g_Q);
    cudaGetSymbolAddress((void**)&Kp, g_K);
    cudaGetSymbolAddress((void**)&Vp, g_V);
    cudaGetSymbolAddress((void**)&Cp, g_CTX);

    // QKV projections (tensor-core split-bf16)
    gemm_bf16x3<<<dim3(QCOLS / 128, NTOK / 128), 256>>>(hidden, Wq, Qp, NTOK, QCOLS, HID);
    gemm_bf16x3<<<dim3(KVCOLS / 128, NTOK / 128), 256>>>(hidden, Wk, Kp, NTOK, KVCOLS, HID);
    gemm_bf16x3<<<dim3(KVCOLS / 128, NTOK / 128), 256>>>(hidden, Wv, Vp, NTOK, KVCOLS, HID);

    // RMSNorm + RoPE
    rmsrope_kernel<<<NTOK * NH, 128>>>(Qp, qw, pos, NH);
    rmsrope_kernel<<<NTOK * NKV, 128>>>(Kp, kw, pos, NKV);

    // Tensor-core flash attention
    cudaFuncSetAttribute(attn_tc_kernel, cudaFuncAttributeMaxDynamicSharedMemorySize, ATTN_SMEM);
    attn_tc_kernel<<<dim3(SEQ / 128, NH, BATCH), 256, ATTN_SMEM>>>(Qp, Kp, Vp, Cp);

    // Output projection
    gemm_bf16x3<<<dim3(HID / 128, NTOK / 128), 256>>>(Cp, Wo, out, NTOK, HID, QCOLS);
}

// round 4
// speedup vs baseline: 1.5526x; 1.0243x over previous
#include <cuda_runtime.h>
#include <cuda_bf16.h>
#include <math.h>
#include <stdint.h>

// Problem constants
#define BATCH 2
#define SEQ   2048
#define HID   2048
#define NH    32
#define NKV   4
#define HD    128
#define NTOK  (BATCH*SEQ)          // 4096
#define QCOLS (NH*HD)              // 4096
#define KVCOLS (NKV*HD)            // 512

// -------- scratch (device globals: no runtime allocation allowed) --------
__device__ float g_Q[(size_t)NTOK * QCOLS];    // 64 MiB
__device__ float g_K[(size_t)NTOK * KVCOLS];   // 8 MiB
__device__ float g_V[(size_t)NTOK * KVCOLS];   // 8 MiB
__device__ float g_CTX[(size_t)NTOK * QCOLS];  // 64 MiB

// ============================================================================
// PTX helpers
// ============================================================================
__device__ __forceinline__ uint32_t smem_u32(const void* p) {
    return (uint32_t)__cvta_generic_to_shared(p);
}
__device__ __forceinline__ void ldmatrix_x4(uint32_t* r, uint32_t addr) {
    asm volatile("ldmatrix.sync.aligned.m8n8.x4.shared.b16 {%0,%1,%2,%3}, [%4];"
                 : "=r"(r[0]), "=r"(r[1]), "=r"(r[2]), "=r"(r[3]) : "r"(addr));
}
__device__ __forceinline__ void ldmatrix_x4_trans(uint32_t* r, uint32_t addr) {
    asm volatile("ldmatrix.sync.aligned.m8n8.x4.trans.shared.b16 {%0,%1,%2,%3}, [%4];"
                 : "=r"(r[0]), "=r"(r[1]), "=r"(r[2]), "=r"(r[3]) : "r"(addr));
}
__device__ __forceinline__ void mma_bf16(float* d, const uint32_t* a, const uint32_t* b) {
    asm volatile("mma.sync.aligned.m16n8k16.row.col.f32.bf16.bf16.f32 "
                 "{%0,%1,%2,%3}, {%4,%5,%6,%7}, {%8,%9}, {%0,%1,%2,%3};"
                 : "+f"(d[0]), "+f"(d[1]), "+f"(d[2]), "+f"(d[3])
                 : "r"(a[0]), "r"(a[1]), "r"(a[2]), "r"(a[3]),
                   "r"(b[0]), "r"(b[1]));
}
__device__ __forceinline__ void split2(float x, __nv_bfloat16& h, __nv_bfloat16& l) {
    h = __float2bfloat16_rn(x);
    l = __float2bfloat16_rn(x - __bfloat162float(h));
}
__device__ __forceinline__ uint32_t pack_bf16x2(float lo, float hi) {
    __nv_bfloat162 r = __floats2bfloat162_rn(lo, hi);
    return *(uint32_t*)&r;
}
// split a float4 into packed hi (uint2) and lo (uint2): 4 bf16 each
__device__ __forceinline__ void split4_pack(float4 v, uint2& hh, uint2& ll) {
    __nv_bfloat16 hx, lx, hy, ly, hz, lz, hw, lw;
    split2(v.x, hx, lx); split2(v.y, hy, ly);
    split2(v.z, hz, lz); split2(v.w, hw, lw);
    hh.x = pack_bf16x2(__bfloat162float(hx), __bfloat162float(hy));
    hh.y = pack_bf16x2(__bfloat162float(hz), __bfloat162float(hw));
    ll.x = pack_bf16x2(__bfloat162float(lx), __bfloat162float(ly));
    ll.y = pack_bf16x2(__bfloat162float(lz), __bfloat162float(lw));
}
__device__ __forceinline__ void cp_async16(uint32_t dst, const void* src) {
    asm volatile("cp.async.cg.shared.global [%0], [%1], 16;" :: "r"(dst), "l"(src));
}
#define CP_COMMIT asm volatile("cp.async.commit_group;")
#define CP_WAIT0  asm volatile("cp.async.wait_group 0;" ::: "memory")

// ============================================================================
// Pipelined GEMM via split-bf16 tensor cores: C = A[M,K] @ B[K,N], fp32 io.
// 128x128 tile, BK=32, 256 threads, double-buffered smem + register prefetch.
// ============================================================================
#define ASTR 40
#define BSTR 136
#define GEMM_BUF_ELE (128*ASTR*2 + 32*BSTR*2)        // bf16 elems per buffer
#define GEMM_SMEM    (2 * GEMM_BUF_ELE * 2)          // bytes

__global__ __launch_bounds__(256, 2)
void gemm_bf16x3(const float* __restrict__ A, const float* __restrict__ Bm,
                 float* __restrict__ C, int M, int N, int K)
{
    extern __shared__ __nv_bfloat16 smg[];

    const int tid  = threadIdx.x;
    const int warp = tid >> 5;
    const int lane = tid & 31;
    const int wm = (warp >> 1) * 32;
    const int wn = (warp & 1) * 64;
    const int bx = blockIdx.x * 128;
    const int by = blockIdx.y * 128;

    const int ar = tid >> 1;
    const int ac = (tid & 1) * 16;
    const int br = tid >> 3;
    const int bc = (tid & 7) * 16;

    float acc[2][8][4];
    #pragma unroll
    for (int mi = 0; mi < 2; mi++)
        #pragma unroll
        for (int ni = 0; ni < 8; ni++)
            #pragma unroll
            for (int e = 0; e < 4; e++) acc[mi][ni][e] = 0.f;

    const float* Aptr = A + (size_t)(by + ar) * K;
    const float* Bptr = Bm + bx;

    // lane-invariant fragment offsets (in elements)
    const int aoff = (wm + (lane & 15)) * ASTR + ((lane >> 4) << 3);
    const int boff = (lane & 15) * BSTR + wn + ((lane >> 4) << 3);

    float4 pa[4], pb[4];
    const int NIT = K >> 5;

    // ---- prologue: load tile 0 ----
    #pragma unroll
    for (int u = 0; u < 4; u++) {
        pa[u] = *(const float4*)(Aptr + ac + 4 * u);
        pb[u] = *(const float4*)(Bptr + (size_t)(br) * N + bc + 4 * u);
    }
    {
        __nv_bfloat16* Ah = smg;
        __nv_bfloat16* Al = Ah + 128 * ASTR;
        __nv_bfloat16* Bh = Al + 128 * ASTR;
        __nv_bfloat16* Bl = Bh + 32 * BSTR;
        #pragma unroll
        for (int u = 0; u < 4; u++) {
            uint2 hh, ll;
            split4_pack(pa[u], hh, ll);
            *(uint2*)&Ah[ar * ASTR + ac + 4 * u] = hh;
            *(uint2*)&Al[ar * ASTR + ac + 4 * u] = ll;
            split4_pack(pb[u], hh, ll);
            *(uint2*)&Bh[br * BSTR + bc + 4 * u] = hh;
            *(uint2*)&Bl[br * BSTR + bc + 4 * u] = ll;
        }
    }
    __syncthreads();

    for (int it = 0; it < NIT; it++) {
        // ---- prefetch next tile into registers ----
        if (it + 1 < NIT) {
            const int k0 = (it + 1) * 32;
            #pragma unroll
            for (int u = 0; u < 4; u++) {
                pa[u] = *(const float4*)(Aptr + k0 + ac + 4 * u);
                pb[u] = *(const float4*)(Bptr + (size_t)(k0 + br) * N + bc + 4 * u);
            }
        }

        // ---- compute on current buffer ----
        __nv_bfloat16* buf = smg + (it & 1) * GEMM_BUF_ELE;
        const uint32_t Ah_b = smem_u32(buf);
        const uint32_t Al_b = Ah_b + 128 * ASTR * 2;
        const uint32_t Bh_b = Al_b + 128 * ASTR * 2;
        const uint32_t Bl_b = Bh_b + 32 * BSTR * 2;

        #pragma unroll
        for (int kk = 0; kk < 32; kk += 16) {
            uint32_t ah[2][4], al[2][4];
            #pragma unroll
            for (int mi = 0; mi < 2; mi++) {
                ldmatrix_x4(ah[mi], Ah_b + (aoff + mi * 16 * ASTR + kk) * 2);
                ldmatrix_x4(al[mi], Al_b + (aoff + mi * 16 * ASTR + kk) * 2);
            }
            #pragma unroll
            for (int p = 0; p < 4; p++) {
                uint32_t bh[4], bl[4];
                const uint32_t off = (boff + kk * BSTR + p * 16) * 2;
                ldmatrix_x4_trans(bh, Bh_b + off);
                ldmatrix_x4_trans(bl, Bl_b + off);
                #pragma unroll
                for (int mi = 0; mi < 2; mi++) {
                    mma_bf16(acc[mi][2*p],   ah[mi], bh);
                    mma_bf16(acc[mi][2*p],   ah[mi], bl);
                    mma_bf16(acc[mi][2*p],   al[mi], bh);
                    mma_bf16(acc[mi][2*p+1], ah[mi], bh + 2);
                    mma_bf16(acc[mi][2*p+1], ah[mi], bl + 2);
                    mma_bf16(acc[mi][2*p+1], al[mi], bh + 2);
                }
            }
        }

        // ---- store prefetched tile into the other (free) buffer ----
        if (it + 1 < NIT) {
            __nv_bfloat16* nb = smg + ((it + 1) & 1) * GEMM_BUF_ELE;
            __nv_bfloat16* Ah = nb;
            __nv_bfloat16* Al = Ah + 128 * ASTR;
            __nv_bfloat16* Bh = Al + 128 * ASTR;
            __nv_bfloat16* Bl = Bh + 32 * BSTR;
            #pragma unroll
            for (int u = 0; u < 4; u++) {
                uint2 hh, ll;
                split4_pack(pa[u], hh, ll);
                *(uint2*)&Ah[ar * ASTR + ac + 4 * u] = hh;
                *(uint2*)&Al[ar * ASTR + ac + 4 * u] = ll;
                split4_pack(pb[u], hh, ll);
                *(uint2*)&Bh[br * BSTR + bc + 4 * u] = hh;
                *(uint2*)&Bl[br * BSTR + bc + 4 * u] = ll;
            }
        }
        __syncthreads();
    }

    const int g = lane >> 2;
    const int t = lane & 3;
    #pragma unroll
    for (int mi = 0; mi < 2; mi++) {
        #pragma unroll
        for (int ni = 0; ni < 8; ni++) {
            const size_t row0 = (size_t)(by + wm + mi * 16 + g);
            const int col = bx + wn + ni * 8 + 2 * t;
            *(float2*)(C + row0 * N + col)       = make_float2(acc[mi][ni][0], acc[mi][ni][1]);
            *(float2*)(C + (row0 + 8) * N + col) = make_float2(acc[mi][ni][2], acc[mi][ni][3]);
        }
    }
}

// ============================================================================
// RMSNorm + RoPE, one block of 128 threads per (token, head). In-place.
// ============================================================================
__global__ __launch_bounds__(128)
void rmsrope_kernel(float* __restrict__ X, const float* __restrict__ w,
                    const int* __restrict__ pos, int nheads)
{
    const int blk = blockIdx.x;
    const int token = blk / nheads;
    const int h     = blk % nheads;
    float* x = X + (size_t)token * (nheads * HD) + h * HD;

    const int i = threadIdx.x;
    float v = x[i];

    float ss = v * v;
    #pragma unroll
    for (int m = 16; m; m >>= 1) ss += __shfl_xor_sync(0xffffffffu, ss, m);
    __shared__ float wsum[4];
    if ((i & 31) == 0) wsum[i >> 5] = ss;
    __syncthreads();
    float tot = wsum[0] + wsum[1] + wsum[2] + wsum[3];
    float inv = rsqrtf(tot * (1.0f / 128.0f) + 1e-6f);

    __shared__ float xs[128];
    xs[i] = v * inv * w[i];
    __syncthreads();

    const int p = pos[token];
    const int j = i & 63;
    float invf = (float)pow(1.0e6, -(double)j / 64.0);
    float f = (float)p * invf;
    float c, s;
    sincosf(f, &s, &c);
    float xi = xs[i];
    float partner = (i < 64) ? -xs[i + 64] : xs[i - 64];
    x[i] = xi * c + partner * s;
}

// ============================================================================
// Tensor-core flash attention (split-bf16, 3-term), causal, cp.async pipelined.
// Br=128 (8 warps x 16 rows), Bc=64, 256 threads. grid=(SEQ/128, NH, B).
// smem: [fp32 staging K 64x128][fp32 staging V 64x128][bf16 arrays]
// ============================================================================
#define QSTR 136
#define KSTR 72
#define VSTR 136
#define STG_FLOATS (64 * 128)
#define ATTN_BF16_OFF (2 * STG_FLOATS)   // in floats
#define ATTN_SMEM (2*STG_FLOATS*4 + (2*128*QSTR + 2*128*KSTR + 2*64*VSTR) * 2)

__global__ __launch_bounds__(256, 1)
void attn_tc_kernel(const float* __restrict__ Q, const float* __restrict__ K,
                    const float* __restrict__ V, float* __restrict__ CTX)
{
    extern __shared__ float smf[];
    float* KsF = smf;                       // [64][128] fp32 staging
    float* VsF = KsF + STG_FLOATS;
    __nv_bfloat16* Qh  = (__nv_bfloat16*)(smf + ATTN_BF16_OFF);
    __nv_bfloat16* Ql  = Qh  + 128 * QSTR;
    __nv_bfloat16* Kth = Ql  + 128 * QSTR;   // [d][token]
    __nv_bfloat16* Ktl = Kth + 128 * KSTR;
    __nv_bfloat16* Vh  = Ktl + 128 * KSTR;   // [token][d]
    __nv_bfloat16* Vl  = Vh  + 64 * VSTR;

    const int qt = gridDim.x - 1 - blockIdx.x;
    const int h  = blockIdx.y;
    const int b  = blockIdx.z;
    const int hk = h >> 3;

    const int tid  = threadIdx.x;
    const int warp = tid >> 5;
    const int lane = tid & 31;
    const int g  = lane >> 2;
    const int t4 = lane & 3;

    const float scale = 0.08838834764831845f;   // 1/sqrt(128)
    const int ntiles = 2 * qt + 2;

    // KV loader mapping (also used for staging split)
    const int kvc = tid >> 2;               // token 0..63
    const int kvd = (tid & 3) * 32;         // d base

    // ---- issue cp.async for jt=0 ----
    {
        const size_t tok = (size_t)(b * SEQ + kvc);
        const float* ksrc = K + tok * KVCOLS + hk * HD + kvd;
        const float* vsrc = V + tok * KVCOLS + hk * HD + kvd;
        const uint32_t kdst = smem_u32(&KsF[kvc * 128 + kvd]);
        const uint32_t vdst = smem_u32(&VsF[kvc * 128 + kvd]);
        #pragma unroll
        for (int u = 0; u < 8; u++) {
            cp_async16(kdst + u * 16, ksrc + 4 * u);
            cp_async16(vdst + u * 16, vsrc + 4 * u);
        }
        CP_COMMIT;
    }

    // ---- load + split Q tile (128x128), pre-scaled ----
    {
        const int r  = tid >> 1;
        const int c0 = (tid & 1) * 64;
        const float* src = Q + ((size_t)(b * SEQ + qt * 128 + r)) * QCOLS + h * HD + c0;
        #pragma unroll
        for (int u = 0; u < 16; u++) {
            float4 v = *(const float4*)(src + 4 * u);
            const int c = c0 + 4 * u;
            split2(v.x * scale, Qh[r*QSTR + c+0], Ql[r*QSTR + c+0]);
            split2(v.y * scale, Qh[r*QSTR + c+1], Ql[r*QSTR + c+1]);
            split2(v.z * scale, Qh[r*QSTR + c+2], Ql[r*QSTR + c+2]);
            split2(v.w * scale, Qh[r*QSTR + c+3], Ql[r*QSTR + c+3]);
        }
    }

    float oacc[16][4];
    #pragma unroll
    for (int nt = 0; nt < 16; nt++)
        #pragma unroll
        for (int e = 0; e < 4; e++) oacc[nt][e] = 0.f;
    float mrow0 = -1e30f, mrow1 = -1e30f, lrow0 = 0.f, lrow1 = 0.f;

    const int qrow0 = qt * 128 + warp * 16 + g;
    const int qrow1 = qrow0 + 8;
    const int warp_maxrow = qt * 128 + warp * 16 + 15;

    // fragment base addresses
    const uint32_t qh_base  = smem_u32(&Qh [(warp*16 + (lane & 15)) * QSTR + ((lane >> 4) << 3)]);
    const uint32_t ql_base  = smem_u32(&Ql [(warp*16 + (lane & 15)) * QSTR + ((lane >> 4) << 3)]);
    const uint32_t kth_base = smem_u32(&Kth[(lane & 15) * KSTR + ((lane >> 4) << 3)]);
    const uint32_t ktl_base = smem_u32(&Ktl[(lane & 15) * KSTR + ((lane >> 4) << 3)]);
    const uint32_t vh_base  = smem_u32(&Vh [(lane & 15) * VSTR + ((lane >> 4) << 3)]);
    const uint32_t vl_base  = smem_u32(&Vl [(lane & 15) * VSTR + ((lane >> 4) << 3)]);

    for (int jt = 0; jt < ntiles; jt++) {
        CP_WAIT0;
        __syncthreads();   // staging ready; previous compute's smem reads done

        // ---- split staging (smem fp32) -> bf16 arrays ----
        {
            const float* kst = &KsF[kvc * 128 + kvd];
            const float* vst = &VsF[kvc * 128 + kvd];
            #pragma unroll
            for (int u = 0; u < 8; u++) {
                float4 kv = *(const float4*)(kst + 4 * u);
                const int d = kvd + 4 * u;
                split2(kv.x, Kth[(d+0)*KSTR + kvc], Ktl[(d+0)*KSTR + kvc]);
                split2(kv.y, Kth[(d+1)*KSTR + kvc], Ktl[(d+1)*KSTR + kvc]);
                split2(kv.z, Kth[(d+2)*KSTR + kvc], Ktl[(d+2)*KSTR + kvc]);
                split2(kv.w, Kth[(d+3)*KSTR + kvc], Ktl[(d+3)*KSTR + kvc]);
                float4 vv = *(const float4*)(vst + 4 * u);
                split2(vv.x, Vh[kvc*VSTR + d+0], Vl[kvc*VSTR + d+0]);
                split2(vv.y, Vh[kvc*VSTR + d+1], Vl[kvc*VSTR + d+1]);
                split2(vv.z, Vh[kvc*VSTR + d+2], Vl[kvc*VSTR + d+2]);
                split2(vv.w, Vh[kvc*VSTR + d+3], Vl[kvc*VSTR + d+3]);
            }
        }
        __syncthreads();

        // ---- issue cp.async for next tile (staging now free) ----
        if (jt + 1 < ntiles) {
            const size_t tok = (size_t)(b * SEQ + (jt + 1) * 64 + kvc);
            const float* ksrc = K + tok * KVCOLS + hk * HD + kvd;
            const float* vsrc = V + tok * KVCOLS + hk * HD + kvd;
            const uint32_t kdst = smem_u32(&KsF[kvc * 128 + kvd]);
            const uint32_t vdst = smem_u32(&VsF[kvc * 128 + kvd]);
            #pragma unroll
            for (int u = 0; u < 8; u++) {
                cp_async16(kdst + u * 16, ksrc + 4 * u);
                cp_async16(vdst + u * 16, vsrc + 4 * u);
            }
            CP_COMMIT;
        }

        // per-warp skip of fully-masked tiles (warp-uniform branch)
        if (jt * 64 > warp_maxrow) continue;

        // ---- S = Q @ Kt ----
        float sacc[8][4];
        #pragma unroll
        for (int nt = 0; nt < 8; nt++)
            #pragma unroll
            for (int e = 0; e < 4; e++) sacc[nt][e] = 0.f;

        #pragma unroll
        for (int kk = 0; kk < 8; kk++) {
            uint32_t ah[4], al[4];
            ldmatrix_x4(ah, qh_base + kk * 16 * sizeof(__nv_bfloat16));
            ldmatrix_x4(al, ql_base + kk * 16 * sizeof(__nv_bfloat16));
            #pragma unroll
            for (int p = 0; p < 4; p++) {
                uint32_t bh[4], bl[4];
                const uint32_t off = (kk * 16 * KSTR + p * 16) * sizeof(__nv_bfloat16);
                ldmatrix_x4_trans(bh, kth_base + off);
                ldmatrix_x4_trans(bl, ktl_base + off);
                mma_bf16(sacc[2*p],   ah, bh);
                mma_bf16(sacc[2*p],   ah, bl);
                mma_bf16(sacc[2*p],   al, bh);
                mma_bf16(sacc[2*p+1], ah, bh + 2);
                mma_bf16(sacc[2*p+1], ah, bl + 2);
                mma_bf16(sacc[2*p+1], al, bh + 2);
            }
        }

        // ---- causal mask + online softmax on fragments ----
        float mx0 = -1e30f, mx1 = -1e30f;
        #pragma unroll
        for (int nt = 0; nt < 8; nt++) {
            const int col = jt * 64 + nt * 8 + 2 * t4;
            if (col     > qrow0) sacc[nt][0] = -1e30f;
            if (col + 1 > qrow0) sacc[nt][1] = -1e30f;
            if (col     > qrow1) sacc[nt][2] = -1e30f;
            if (col + 1 > qrow1) sacc[nt][3] = -1e30f;
            mx0 = fmaxf(mx0, fmaxf(sacc[nt][0], sacc[nt][1]));
            mx1 = fmaxf(mx1, fmaxf(sacc[nt][2], sacc[nt][3]));
        }
        mx0 = fmaxf(mx0, __shfl_xor_sync(0xffffffffu, mx0, 1));
        mx0 = fmaxf(mx0, __shfl_xor_sync(0xffffffffu, mx0, 2));
        mx1 = fmaxf(mx1, __shfl_xor_sync(0xffffffffu, mx1, 1));
        mx1 = fmaxf(mx1, __shfl_xor_sync(0xffffffffu, mx1, 2));

        const float mnew0 = fmaxf(mrow0, mx0);
        const float mnew1 = fmaxf(mrow1, mx1);
        const float alpha0 = __expf(mrow0 - mnew0);
        const float alpha1 = __expf(mrow1 - mnew1);

        float rs0 = 0.f, rs1 = 0.f;
        #pragma unroll
        for (int nt = 0; nt < 8; nt++) {
            sacc[nt][0] = __expf(sacc[nt][0] - mnew0);
            sacc[nt][1] = __expf(sacc[nt][1] - mnew0);
            sacc[nt][2] = __expf(sacc[nt][2] - mnew1);
            sacc[nt][3] = __expf(sacc[nt][3] - mnew1);
            rs0 += sacc[nt][0] + sacc[nt][1];
            rs1 += sacc[nt][2] + sacc[nt][3];
        }
        rs0 += __shfl_xor_sync(0xffffffffu, rs0, 1);
        rs0 += __shfl_xor_sync(0xffffffffu, rs0, 2);
        rs1 += __shfl_xor_sync(0xffffffffu, rs1, 1);
        rs1 += __shfl_xor_sync(0xffffffffu, rs1, 2);

        lrow0 = lrow0 * alpha0 + rs0;
        lrow1 = lrow1 * alpha1 + rs1;
        mrow0 = mnew0;
        mrow1 = mnew1;

        #pragma unroll
        for (int nt = 0; nt < 16; nt++) {
            oacc[nt][0] *= alpha0;
            oacc[nt][1] *= alpha0;
            oacc[nt][2] *= alpha1;
            oacc[nt][3] *= alpha1;
        }

        // ---- O += P @ V : pack P from sacc registers (FA2 identity) ----
        #pragma unroll
        for (int c = 0; c < 4; c++) {
            uint32_t ph[4], pl[4];
            {
                __nv_bfloat16 h00, l00, h01, l01, h02, l02, h03, l03;
                __nv_bfloat16 h10, l10, h11, l11, h12, l12, h13, l13;
                split2(sacc[2*c][0],   h00, l00); split2(sacc[2*c][1],   h01, l01);
                split2(sacc[2*c][2],   h02, l02); split2(sacc[2*c][3],   h03, l03);
                split2(sacc[2*c+1][0], h10, l10); split2(sacc[2*c+1][1], h11, l11);
                split2(sacc[2*c+1][2], h12, l12); split2(sacc[2*c+1][3], h13, l13);
                ph[0] = pack_bf16x2(__bfloat162float(h00), __bfloat162float(h01));
                ph[1] = pack_bf16x2(__bfloat162float(h02), __bfloat162float(h03));
                ph[2] = pack_bf16x2(__bfloat162float(h10), __bfloat162float(h11));
                ph[3] = pack_bf16x2(__bfloat162float(h12), __bfloat162float(h13));
                pl[0] = pack_bf16x2(__bfloat162float(l00), __bfloat162float(l01));
                pl[1] = pack_bf16x2(__bfloat162float(l02), __bfloat162float(l03));
                pl[2] = pack_bf16x2(__bfloat162float(l10), __bfloat162float(l11));
                pl[3] = pack_bf16x2(__bfloat162float(l12), __bfloat162float(l13));
            }
            #pragma unroll
            for (int p = 0; p < 8; p++) {
                uint32_t vh[4], vl[4];
                const uint32_t off = (c * 16 * VSTR + p * 16) * sizeof(__nv_bfloat16);
                ldmatrix_x4_trans(vh, vh_base + off);
                ldmatrix_x4_trans(vl, vl_base + off);
                mma_bf16(oacc[2*p],   ph, vh);
                mma_bf16(oacc[2*p],   pl, vh);
                mma_bf16(oacc[2*p],   ph, vl);
                mma_bf16(oacc[2*p+1], ph, vh + 2);
                mma_bf16(oacc[2*p+1], pl, vh + 2);
                mma_bf16(oacc[2*p+1], ph, vl + 2);
            }
        }
    }

    // ---- epilogue ----
    const float inv0 = 1.0f / lrow0;
    const float inv1 = 1.0f / lrow1;
    float* dst0 = CTX + ((size_t)(b * SEQ + qrow0)) * QCOLS + h * HD;
    float* dst1 = CTX + ((size_t)(b * SEQ + qrow1)) * QCOLS + h * HD;
    #pragma unroll
    for (int nt = 0; nt < 16; nt++) {
        const int col = nt * 8 + 2 * t4;
        *(float2*)(dst0 + col) = make_float2(oacc[nt][0] * inv0, oacc[nt][1] * inv0);
        *(float2*)(dst1 + col) = make_float2(oacc[nt][2] * inv1, oacc[nt][3] * inv1);
    }
}

// ============================================================================
// Launch
// ============================================================================
extern "C" void kernel_launch(void* const* d_in, const int* in_sizes, int n_in,
                              void* d_out, int out_size)
{
    const float* hidden = (const float*)d_in[0];
    const int*   pos    = (const int*)  d_in[2];
    const float* Wq     = (const float*)d_in[3];
    const float* Wk     = (const float*)d_in[4];
    const float* Wv     = (const float*)d_in[5];
    const float* Wo     = (const float*)d_in[6];
    const float* qw     = (const float*)d_in[7];
    const float* kw     = (const float*)d_in[8];
    float* out = (float*)d_out;

    float *Qp, *Kp, *Vp, *Cp;
    cudaGetSymbolAddress((void**)&Qp, g_Q);
    cudaGetSymbolAddress((void**)&Kp, g_K);
    cudaGetSymbolAddress((void**)&Vp, g_V);
    cudaGetSymbolAddress((void**)&Cp, g_CTX);

    cudaFuncSetAttribute(gemm_bf16x3, cudaFuncAttributeMaxDynamicSharedMemorySize, GEMM_SMEM);
    cudaFuncSetAttribute(attn_tc_kernel, cudaFuncAttributeMaxDynamicSharedMemorySize, ATTN_SMEM);

    // QKV projections (pipelined tensor-core split-bf16)
    gemm_bf16x3<<<dim3(QCOLS / 128, NTOK / 128), 256, GEMM_SMEM>>>(hidden, Wq, Qp, NTOK, QCOLS, HID);
    gemm_bf16x3<<<dim3(KVCOLS / 128, NTOK / 128), 256, GEMM_SMEM>>>(hidden, Wk, Kp, NTOK, KVCOLS, HID);
    gemm_bf16x3<<<dim3(KVCOLS / 128, NTOK / 128), 256, GEMM_SMEM>>>(hidden, Wv, Vp, NTOK, KVCOLS, HID);

    // RMSNorm + RoPE
    rmsrope_kernel<<<NTOK * NH, 128>>>(Qp, qw, pos, NH);
    rmsrope_kernel<<<NTOK * NKV, 128>>>(Kp, kw, pos, NKV);

    // Tensor-core flash attention (cp.async pipelined)
    attn_tc_kernel<<<dim3(SEQ / 128, NH, BATCH), 256, ATTN_SMEM>>>(Qp, Kp, Vp, Cp);

    // Output projection
    gemm_bf16x3<<<dim3(HID / 128, NTOK / 128), 256, GEMM_SMEM>>>(Cp, Wo, out, NTOK, HID, QCOLS);
}

// round 7
// speedup vs baseline: 1.9342x; 1.2458x over previous
#include <cuda_runtime.h>
#include <cuda_bf16.h>
#include <math.h>
#include <stdint.h>

// Problem constants
#define BATCH 2
#define SEQ   2048
#define HID   2048
#define NH    32
#define NKV   4
#define HD    128
#define NTOK  (BATCH*SEQ)          // 4096
#define QCOLS (NH*HD)              // 4096
#define KVCOLS (NKV*HD)            // 512

typedef __nv_bfloat16 bf16;

// -------- scratch (device globals: no runtime allocation allowed) --------
__device__ float g_Q[(size_t)NTOK * QCOLS];    // 64 MiB
__device__ float g_K[(size_t)NTOK * KVCOLS];   // 8 MiB
__device__ float g_V[(size_t)NTOK * KVCOLS];   // 8 MiB
__device__ float g_CTX[(size_t)NTOK * QCOLS];  // 64 MiB
// pre-split bf16 operands
__device__ bf16 g_Hh[(size_t)NTOK * HID],   g_Hl[(size_t)NTOK * HID];     // hidden
__device__ bf16 g_Wh[(size_t)HID * QCOLS],  g_Wl[(size_t)HID * QCOLS];    // current weight
__device__ bf16 g_Ch[(size_t)NTOK * QCOLS], g_Cl[(size_t)NTOK * QCOLS];   // ctx
__device__ bf16 g_KthH[(size_t)BATCH*NKV*HD*SEQ], g_KthL[(size_t)BATCH*NKV*HD*SEQ]; // K transposed
__device__ bf16 g_VhS[(size_t)NTOK * KVCOLS], g_VlS[(size_t)NTOK * KVCOLS];

// ============================================================================
// PTX helpers
// ============================================================================
__device__ __forceinline__ uint32_t smem_u32(const void* p) {
    return (uint32_t)__cvta_generic_to_shared(p);
}
__device__ __forceinline__ void ldmatrix_x4(uint32_t* r, uint32_t addr) {
    asm volatile("ldmatrix.sync.aligned.m8n8.x4.shared.b16 {%0,%1,%2,%3}, [%4];"
                 : "=r"(r[0]), "=r"(r[1]), "=r"(r[2]), "=r"(r[3]) : "r"(addr));
}
__device__ __forceinline__ void ldmatrix_x4_trans(uint32_t* r, uint32_t addr) {
    asm volatile("ldmatrix.sync.aligned.m8n8.x4.trans.shared.b16 {%0,%1,%2,%3}, [%4];"
                 : "=r"(r[0]), "=r"(r[1]), "=r"(r[2]), "=r"(r[3]) : "r"(addr));
}
__device__ __forceinline__ void mma_bf16(float* d, const uint32_t* a, const uint32_t* b) {
    asm volatile("mma.sync.aligned.m16n8k16.row.col.f32.bf16.bf16.f32 "
                 "{%0,%1,%2,%3}, {%4,%5,%6,%7}, {%8,%9}, {%0,%1,%2,%3};"
                 : "+f"(d[0]), "+f"(d[1]), "+f"(d[2]), "+f"(d[3])
                 : "r"(a[0]), "r"(a[1]), "r"(a[2]), "r"(a[3]),
                   "r"(b[0]), "r"(b[1]));
}
__device__ __forceinline__ void split2(float x, bf16& h, bf16& l) {
    h = __float2bfloat16_rn(x);
    l = __float2bfloat16_rn(x - __bfloat162float(h));
}
__device__ __forceinline__ uint32_t pack_bf16x2(float lo, float hi) {
    __nv_bfloat162 r = __floats2bfloat162_rn(lo, hi);
    return *(uint32_t*)&r;
}
__device__ __forceinline__ void split4_pack(float4 v, uint2& hh, uint2& ll) {
    bf16 hx, lx, hy, ly, hz, lz, hw, lw;
    split2(v.x, hx, lx); split2(v.y, hy, ly);
    split2(v.z, hz, lz); split2(v.w, hw, lw);
    hh.x = pack_bf16x2(__bfloat162float(hx), __bfloat162float(hy));
    hh.y = pack_bf16x2(__bfloat162float(hz), __bfloat162float(hw));
    ll.x = pack_bf16x2(__bfloat162float(lx), __bfloat162float(ly));
    ll.y = pack_bf16x2(__bfloat162float(lz), __bfloat162float(lw));
}
__device__ __forceinline__ void cp_async16(uint32_t dst, const void* src) {
    asm volatile("cp.async.cg.shared.global [%0], [%1], 16;" :: "r"(dst), "l"(src));
}
#define CP_COMMIT asm volatile("cp.async.commit_group;")
#define CP_WAIT0  asm volatile("cp.async.wait_group 0;" ::: "memory")
#define CP_WAIT1  asm volatile("cp.async.wait_group 1;" ::: "memory")

// ============================================================================
// Split kernels (memory-bound, one-shot)
// ============================================================================
__global__ __launch_bounds__(256)
void split_mat(const float* __restrict__ src, bf16* __restrict__ dh,
               bf16* __restrict__ dl, int n4)
{
    const int i = blockIdx.x * 256 + threadIdx.x;
    if (i < n4) {
        float4 v = ((const float4*)src)[i];
        uint2 hh, ll;
        split4_pack(v, hh, ll);
        ((uint2*)dh)[i] = hh;
        ((uint2*)dl)[i] = ll;
    }
}

// K fp32 [b*S+tok][hk*128+d]  ->  Kth bf16 [(b*NKV+hk)*128+d][tok]
__global__ __launch_bounds__(256)
void split_k_trans(const float* __restrict__ Ksrc, bf16* __restrict__ dh,
                   bf16* __restrict__ dl)
{
    const int blk = blockIdx.x;          // 0..BATCH*NKV*HD-1
    const int bhk = blk >> 7;
    const int d   = blk & 127;
    const int b   = bhk >> 2, hk = bhk & 3;
    const int t0  = threadIdx.x * 8;
    const float* src = Ksrc + ((size_t)b * SEQ + t0) * KVCOLS + hk * HD + d;
    __align__(16) bf16 h8[8];
    __align__(16) bf16 l8[8];
    #pragma unroll
    for (int j = 0; j < 8; j++) split2(src[(size_t)j * KVCOLS], h8[j], l8[j]);
    const size_t o = ((size_t)bhk * HD + d) * SEQ + t0;
    *(uint4*)&dh[o] = *(uint4*)h8;
    *(uint4*)&dl[o] = *(uint4*)l8;
}

// ============================================================================
// GEMM on pre-split bf16: C[M,N] = Ah*Bh + Ah*Bl + Al*Bh  (fp32 out)
// 128x128 tile, BK=32, 256 threads, cp.async double-buffered.
// ============================================================================
#define ASTR 40
#define BSTR 136
#define GB_A_H 0
#define GB_A_L 10240
#define GB_B_H 20480
#define GB_B_L 29184
#define GB_SZ  37888
#define GEMM_SMEM (2 * GB_SZ)

__global__ __launch_bounds__(256, 2)
void gemm_pre(const bf16* __restrict__ Ah_g, const bf16* __restrict__ Al_g,
              const bf16* __restrict__ Bh_g, const bf16* __restrict__ Bl_g,
              float* __restrict__ C, int M, int N, int K)
{
    extern __shared__ char smg[];
    const uint32_t sb = smem_u32(smg);

    const int tid  = threadIdx.x;
    const int warp = tid >> 5;
    const int lane = tid & 31;
    const int wm = (warp >> 1) * 32;
    const int wn = (warp & 1) * 64;
    const int bx = blockIdx.x * 128;
    const int by = blockIdx.y * 128;

    float acc[2][8][4];
    #pragma unroll
    for (int mi = 0; mi < 2; mi++)
        #pragma unroll
        for (int ni = 0; ni < 8; ni++)
            #pragma unroll
            for (int e = 0; e < 4; e++) acc[mi][ni][e] = 0.f;

    // loader mapping
    const int ar = tid >> 1, acb = (tid & 1) * 16;    // A row, col base (elems)
    const int brw = tid >> 3, bcb = (tid & 7) * 16;   // B row, col base (elems)

    auto issue_tile = [&](int k0, uint32_t bufb) {
        const bf16* a_h = Ah_g + (size_t)(by + ar) * K + k0 + acb;
        const bf16* a_l = Al_g + (size_t)(by + ar) * K + k0 + acb;
        const uint32_t da = bufb + GB_A_H + (uint32_t)(ar * 80 + acb * 2);
        const uint32_t dal = bufb + GB_A_L + (uint32_t)(ar * 80 + acb * 2);
        cp_async16(da,       a_h);
        cp_async16(da + 16,  a_h + 8);
        cp_async16(dal,      a_l);
        cp_async16(dal + 16, a_l + 8);
        const bf16* b_h = Bh_g + (size_t)(k0 + brw) * N + bx + bcb;
        const bf16* b_l = Bl_g + (size_t)(k0 + brw) * N + bx + bcb;
        const uint32_t db  = bufb + GB_B_H + (uint32_t)(brw * 272 + bcb * 2);
        const uint32_t dbl = bufb + GB_B_L + (uint32_t)(brw * 272 + bcb * 2);
        cp_async16(db,       b_h);
        cp_async16(db + 16,  b_h + 8);
        cp_async16(dbl,      b_l);
        cp_async16(dbl + 16, b_l + 8);
    };

    const int aoff = (wm + (lane & 15)) * ASTR + ((lane >> 4) << 3);
    const int boff = (lane & 15) * BSTR + wn + ((lane >> 4) << 3);

    const int NIT = K >> 5;
    issue_tile(0, sb);
    CP_COMMIT;

    for (int t = 0; t < NIT; t++) {
        __syncthreads();                       // buffer (t+1)&1 free (compute t-1 done)
        if (t + 1 < NIT) {
            issue_tile((t + 1) * 32, sb + ((t + 1) & 1) * GB_SZ);
            CP_COMMIT;
            CP_WAIT1;
        } else {
            CP_WAIT0;
        }
        __syncthreads();                       // buffer t&1 filled & visible

        const uint32_t bufb = sb + (t & 1) * GB_SZ;
        const uint32_t Ah_b = bufb + GB_A_H;
        const uint32_t Al_b = bufb + GB_A_L;
        const uint32_t Bh_b = bufb + GB_B_H;
        const uint32_t Bl_b = bufb + GB_B_L;

        #pragma unroll
        for (int kk = 0; kk < 32; kk += 16) {
            uint32_t ah[2][4], al[2][4];
            #pragma unroll
            for (int mi = 0; mi < 2; mi++) {
                ldmatrix_x4(ah[mi], Ah_b + (aoff + mi * 16 * ASTR + kk) * 2);
                ldmatrix_x4(al[mi], Al_b + (aoff + mi * 16 * ASTR + kk) * 2);
            }
            #pragma unroll
            for (int p = 0; p < 4; p++) {
                uint32_t bh[4], bl[4];
                const uint32_t off = (boff + kk * BSTR + p * 16) * 2;
                ldmatrix_x4_trans(bh, Bh_b + off);
                ldmatrix_x4_trans(bl, Bl_b + off);
                #pragma unroll
                for (int mi = 0; mi < 2; mi++) {
                    mma_bf16(acc[mi][2*p],   ah[mi], bh);
                    mma_bf16(acc[mi][2*p],   ah[mi], bl);
                    mma_bf16(acc[mi][2*p],   al[mi], bh);
                    mma_bf16(acc[mi][2*p+1], ah[mi], bh + 2);
                    mma_bf16(acc[mi][2*p+1], ah[mi], bl + 2);
                    mma_bf16(acc[mi][2*p+1], al[mi], bh + 2);
                }
            }
        }
    }

    const int g = lane >> 2;
    const int t = lane & 3;
    #pragma unroll
    for (int mi = 0; mi < 2; mi++) {
        #pragma unroll
        for (int ni = 0; ni < 8; ni++) {
            const size_t row0 = (size_t)(by + wm + mi * 16 + g);
            const int col = bx + wn + ni * 8 + 2 * t;
            *(float2*)(C + row0 * N + col)       = make_float2(acc[mi][ni][0], acc[mi][ni][1]);
            *(float2*)(C + (row0 + 8) * N + col) = make_float2(acc[mi][ni][2], acc[mi][ni][3]);
        }
    }
}

// ============================================================================
// RMSNorm + RoPE, one block of 128 threads per (token, head). In-place.
// ============================================================================
__global__ __launch_bounds__(128)
void rmsrope_kernel(float* __restrict__ X, const float* __restrict__ w,
                    const int* __restrict__ pos, int nheads)
{
    const int blk = blockIdx.x;
    const int token = blk / nheads;
    const int h     = blk % nheads;
    float* x = X + (size_t)token * (nheads * HD) + h * HD;

    const int i = threadIdx.x;
    float v = x[i];

    float ss = v * v;
    #pragma unroll
    for (int m = 16; m; m >>= 1) ss += __shfl_xor_sync(0xffffffffu, ss, m);
    __shared__ float wsum[4];
    if ((i & 31) == 0) wsum[i >> 5] = ss;
    __syncthreads();
    float tot = wsum[0] + wsum[1] + wsum[2] + wsum[3];
    float inv = rsqrtf(tot * (1.0f / 128.0f) + 1e-6f);

    __shared__ float xs[128];
    xs[i] = v * inv * w[i];
    __syncthreads();

    const int p = pos[token];
    const int j = i & 63;
    float invf = (float)pow(1.0e6, -(double)j / 64.0);
    float f = (float)p * invf;
    float c, s;
    sincosf(f, &s, &c);
    float xi = xs[i];
    float partner = (i < 64) ? -xs[i + 64] : xs[i - 64];
    x[i] = xi * c + partner * s;
}

// ============================================================================
// Tensor-core flash attention on pre-split K/V; Q split in-kernel.
// Br=128 (8 warps x 16 rows), Bc=64, 256 threads, cp.async double-buffered.
// ============================================================================
#define QSTR 136
#define KSTR 72
#define VSTR 136
#define AT_Q_H   0
#define AT_Q_L   (128*QSTR*2)
#define AT_BUF0  (2*128*QSTR*2)
#define AT_KH    0
#define AT_KL    (128*KSTR*2)
#define AT_VH    (2*128*KSTR*2)
#define AT_VL    (2*128*KSTR*2 + 64*VSTR*2)
#define AT_BUFSZ (2*128*KSTR*2 + 2*64*VSTR*2)
#define ATTN_SMEM (AT_BUF0 + 2*AT_BUFSZ)

__global__ __launch_bounds__(256, 1)
void attn_tc_kernel(const float* __restrict__ Q,
                    const bf16* __restrict__ KthH, const bf16* __restrict__ KthL,
                    const bf16* __restrict__ VhG,  const bf16* __restrict__ VlG,
                    float* __restrict__ CTX)
{
    extern __shared__ char sma[];
    const uint32_t sb = smem_u32(sma);
    bf16* Qh = (bf16*)(sma + AT_Q_H);
    bf16* Ql = (bf16*)(sma + AT_Q_L);

    const int qt = gridDim.x - 1 - blockIdx.x;
    const int h  = blockIdx.y;
    const int b  = blockIdx.z;
    const int hk = h >> 3;

    const int tid  = threadIdx.x;
    const int warp = tid >> 5;
    const int lane = tid & 31;
    const int g  = lane >> 2;
    const int t4 = lane & 3;

    const float scale = 0.08838834764831845f;
    const int ntiles = 2 * qt + 2;

    // per-(b,hk) base pointers
    const bf16* kh_g = KthH + (size_t)(b * NKV + hk) * HD * SEQ;
    const bf16* kl_g = KthL + (size_t)(b * NKV + hk) * HD * SEQ;
    const bf16* vh_g = VhG + (size_t)b * SEQ * KVCOLS + hk * HD;
    const bf16* vl_g = VlG + (size_t)b * SEQ * KVCOLS + hk * HD;

    // loader mappings
    const int kd = tid >> 1, kc0 = (tid & 1) * 32;    // K: d-row (0..127), token base
    const int vc = tid >> 2, vd0 = (tid & 3) * 32;    // V: token-row (0..63), d base

    auto issue_kv = [&](int jt, uint32_t bufb) {
        const bf16* kh = kh_g + (size_t)kd * SEQ + jt * 64 + kc0;
        const bf16* kl = kl_g + (size_t)kd * SEQ + jt * 64 + kc0;
        const uint32_t dk  = bufb + AT_KH + (uint32_t)(kd * 144 + kc0 * 2);
        const uint32_t dkl = bufb + AT_KL + (uint32_t)(kd * 144 + kc0 * 2);
        #pragma unroll
        for (int u = 0; u < 4; u++) {
            cp_async16(dk  + u * 16, kh + u * 8);
            cp_async16(dkl + u * 16, kl + u * 8);
        }
        const bf16* vh = vh_g + (size_t)(jt * 64 + vc) * KVCOLS + vd0;
        const bf16* vl = vl_g + (size_t)(jt * 64 + vc) * KVCOLS + vd0;
        const uint32_t dv  = bufb + AT_VH + (uint32_t)(vc * 272 + vd0 * 2);
        const uint32_t dvl = bufb + AT_VL + (uint32_t)(vc * 272 + vd0 * 2);
        #pragma unroll
        for (int u = 0; u < 4; u++) {
            cp_async16(dv  + u * 16, vh + u * 8);
            cp_async16(dvl + u * 16, vl + u * 8);
        }
    };

    // prefetch tile 0, then load+split Q (overlaps cp.async)
    issue_kv(0, sb + AT_BUF0);
    CP_COMMIT;
    {
        const int r  = tid >> 1;
        const int c0 = (tid & 1) * 64;
        const float* src = Q + ((size_t)(b * SEQ + qt * 128 + r)) * QCOLS + h * HD + c0;
        #pragma unroll
        for (int u = 0; u < 16; u++) {
            float4 v = *(const float4*)(src + 4 * u);
            const int c = c0 + 4 * u;
            split2(v.x * scale, Qh[r*QSTR + c+0], Ql[r*QSTR + c+0]);
            split2(v.y * scale, Qh[r*QSTR + c+1], Ql[r*QSTR + c+1]);
            split2(v.z * scale, Qh[r*QSTR + c+2], Ql[r*QSTR + c+2]);
            split2(v.w * scale, Qh[r*QSTR + c+3], Ql[r*QSTR + c+3]);
        }
    }

    float oacc[16][4];
    #pragma unroll
    for (int nt = 0; nt < 16; nt++)
        #pragma unroll
        for (int e = 0; e < 4; e++) oacc[nt][e] = 0.f;
    float mrow0 = -1e30f, mrow1 = -1e30f, lrow0 = 0.f, lrow1 = 0.f;

    const int qrow0 = qt * 128 + warp * 16 + g;
    const int qrow1 = qrow0 + 8;
    const int warp_maxrow = qt * 128 + warp * 16 + 15;

    const uint32_t qh_base = sb + AT_Q_H + ((warp*16 + (lane & 15)) * QSTR + ((lane >> 4) << 3)) * 2;
    const uint32_t ql_base = sb + AT_Q_L + ((warp*16 + (lane & 15)) * QSTR + ((lane >> 4) << 3)) * 2;
    const uint32_t koffB = ((lane & 15) * KSTR + ((lane >> 4) << 3)) * 2;
    const uint32_t voffB = ((lane & 15) * VSTR + ((lane >> 4) << 3)) * 2;

    for (int jt = 0; jt < ntiles; jt++) {
        __syncthreads();                       // buffer (jt+1)&1 free; Q-split visible
        if (jt + 1 < ntiles) {
            issue_kv(jt + 1, sb + AT_BUF0 + ((jt + 1) & 1) * AT_BUFSZ);
            CP_COMMIT;
            CP_WAIT1;
        } else {
            CP_WAIT0;
        }
        __syncthreads();                       // buffer jt&1 ready

        if (jt * 64 > warp_maxrow) continue;   // fully masked for this warp

        const uint32_t bufb = sb + AT_BUF0 + (jt & 1) * AT_BUFSZ;
        const uint32_t kth_b = bufb + AT_KH + koffB;
        const uint32_t ktl_b = bufb + AT_KL + koffB;
        const uint32_t vh_b  = bufb + AT_VH + voffB;
        const uint32_t vl_b  = bufb + AT_VL + voffB;

        // ---- S = Q @ Kt ----
        float sacc[8][4];
        #pragma unroll
        for (int nt = 0; nt < 8; nt++)
            #pragma unroll
            for (int e = 0; e < 4; e++) sacc[nt][e] = 0.f;

        #pragma unroll
        for (int kk = 0; kk < 8; kk++) {
            uint32_t ah[4], al[4];
            ldmatrix_x4(ah, qh_base + kk * 16 * sizeof(bf16));
            ldmatrix_x4(al, ql_base + kk * 16 * sizeof(bf16));
            #pragma unroll
            for (int p = 0; p < 4; p++) {
                uint32_t bh[4], bl[4];
                const uint32_t off = (kk * 16 * KSTR + p * 16) * sizeof(bf16);
                ldmatrix_x4_trans(bh, kth_b + off);
                ldmatrix_x4_trans(bl, ktl_b + off);
                mma_bf16(sacc[2*p],   ah, bh);
                mma_bf16(sacc[2*p],   ah, bl);
                mma_bf16(sacc[2*p],   al, bh);
                mma_bf16(sacc[2*p+1], ah, bh + 2);
                mma_bf16(sacc[2*p+1], ah, bl + 2);
                mma_bf16(sacc[2*p+1], al, bh + 2);
            }
        }

        // ---- causal mask + online softmax ----
        float mx0 = -1e30f, mx1 = -1e30f;
        #pragma unroll
        for (int nt = 0; nt < 8; nt++) {
            const int col = jt * 64 + nt * 8 + 2 * t4;
            if (col     > qrow0) sacc[nt][0] = -1e30f;
            if (col + 1 > qrow0) sacc[nt][1] = -1e30f;
            if (col     > qrow1) sacc[nt][2] = -1e30f;
            if (col + 1 > qrow1) sacc[nt][3] = -1e30f;
            mx0 = fmaxf(mx0, fmaxf(sacc[nt][0], sacc[nt][1]));
            mx1 = fmaxf(mx1, fmaxf(sacc[nt][2], sacc[nt][3]));
        }
        mx0 = fmaxf(mx0, __shfl_xor_sync(0xffffffffu, mx0, 1));
        mx0 = fmaxf(mx0, __shfl_xor_sync(0xffffffffu, mx0, 2));
        mx1 = fmaxf(mx1, __shfl_xor_sync(0xffffffffu, mx1, 1));
        mx1 = fmaxf(mx1, __shfl_xor_sync(0xffffffffu, mx1, 2));

        const float mnew0 = fmaxf(mrow0, mx0);
        const float mnew1 = fmaxf(mrow1, mx1);
        const float alpha0 = __expf(mrow0 - mnew0);
        const float alpha1 = __expf(mrow1 - mnew1);

        float rs0 = 0.f, rs1 = 0.f;
        #pragma unroll
        for (int nt = 0; nt < 8; nt++) {
            sacc[nt][0] = __expf(sacc[nt][0] - mnew0);
            sacc[nt][1] = __expf(sacc[nt][1] - mnew0);
            sacc[nt][2] = __expf(sacc[nt][2] - mnew1);
            sacc[nt][3] = __expf(sacc[nt][3] - mnew1);
            rs0 += sacc[nt][0] + sacc[nt][1];
            rs1 += sacc[nt][2] + sacc[nt][3];
        }
        rs0 += __shfl_xor_sync(0xffffffffu, rs0, 1);
        rs0 += __shfl_xor_sync(0xffffffffu, rs0, 2);
        rs1 += __shfl_xor_sync(0xffffffffu, rs1, 1);
        rs1 += __shfl_xor_sync(0xffffffffu, rs1, 2);

        lrow0 = lrow0 * alpha0 + rs0;
        lrow1 = lrow1 * alpha1 + rs1;
        mrow0 = mnew0;
        mrow1 = mnew1;

        #pragma unroll
        for (int nt = 0; nt < 16; nt++) {
            oacc[nt][0] *= alpha0;
            oacc[nt][1] *= alpha0;
            oacc[nt][2] *= alpha1;
            oacc[nt][3] *= alpha1;
        }

        // ---- O += P @ V ----
        #pragma unroll
        for (int c = 0; c < 4; c++) {
            uint32_t ph[4], pl[4];
            {
                bf16 h00, l00, h01, l01, h02, l02, h03, l03;
                bf16 h10, l10, h11, l11, h12, l12, h13, l13;
                split2(sacc[2*c][0],   h00, l00); split2(sacc[2*c][1],   h01, l01);
                split2(sacc[2*c][2],   h02, l02); split2(sacc[2*c][3],   h03, l03);
                split2(sacc[2*c+1][0], h10, l10); split2(sacc[2*c+1][1], h11, l11);
                split2(sacc[2*c+1][2], h12, l12); split2(sacc[2*c+1][3], h13, l13);
                ph[0] = pack_bf16x2(__bfloat162float(h00), __bfloat162float(h01));
                ph[1] = pack_bf16x2(__bfloat162float(h02), __bfloat162float(h03));
                ph[2] = pack_bf16x2(__bfloat162float(h10), __bfloat162float(h11));
                ph[3] = pack_bf16x2(__bfloat162float(h12), __bfloat162float(h13));
                pl[0] = pack_bf16x2(__bfloat162float(l00), __bfloat162float(l01));
                pl[1] = pack_bf16x2(__bfloat162float(l02), __bfloat162float(l03));
                pl[2] = pack_bf16x2(__bfloat162float(l10), __bfloat162float(l11));
                pl[3] = pack_bf16x2(__bfloat162float(l12), __bfloat162float(l13));
            }
            #pragma unroll
            for (int p = 0; p < 8; p++) {
                uint32_t vh[4], vl[4];
                const uint32_t off = (c * 16 * VSTR + p * 16) * sizeof(bf16);
                ldmatrix_x4_trans(vh, vh_b + off);
                ldmatrix_x4_trans(vl, vl_b + off);
                mma_bf16(oacc[2*p],   ph, vh);
                mma_bf16(oacc[2*p],   pl, vh);
                mma_bf16(oacc[2*p],   ph, vl);
                mma_bf16(oacc[2*p+1], ph, vh + 2);
                mma_bf16(oacc[2*p+1], pl, vh + 2);
                mma_bf16(oacc[2*p+1], ph, vl + 2);
            }
        }
    }

    const float inv0 = 1.0f / lrow0;
    const float inv1 = 1.0f / lrow1;
    float* dst0 = CTX + ((size_t)(b * SEQ + qrow0)) * QCOLS + h * HD;
    float* dst1 = CTX + ((size_t)(b * SEQ + qrow1)) * QCOLS + h * HD;
    #pragma unroll
    for (int nt = 0; nt < 16; nt++) {
        const int col = nt * 8 + 2 * t4;
        *(float2*)(dst0 + col) = make_float2(oacc[nt][0] * inv0, oacc[nt][1] * inv0);
        *(float2*)(dst1 + col) = make_float2(oacc[nt][2] * inv1, oacc[nt][3] * inv1);
    }
}

// ============================================================================
// Launch
// ============================================================================
extern "C" void kernel_launch(void* const* d_in, const int* in_sizes, int n_in,
                              void* d_out, int out_size)
{
    const float* hidden = (const float*)d_in[0];
    const int*   pos    = (const int*)  d_in[2];
    const float* Wq     = (const float*)d_in[3];
    const float* Wk     = (const float*)d_in[4];
    const float* Wv     = (const float*)d_in[5];
    const float* Wo     = (const float*)d_in[6];
    const float* qw     = (const float*)d_in[7];
    const float* kw     = (const float*)d_in[8];
    float* out = (float*)d_out;

    float *Qp, *Kp, *Vp, *Cp;
    bf16 *Hh, *Hl, *Wh, *Wl, *Ch, *Cl, *KtH, *KtL, *Vh, *Vl;
    cudaGetSymbolAddress((void**)&Qp, g_Q);
    cudaGetSymbolAddress((void**)&Kp, g_K);
    cudaGetSymbolAddress((void**)&Vp, g_V);
    cudaGetSymbolAddress((void**)&Cp, g_CTX);
    cudaGetSymbolAddress((void**)&Hh, g_Hh);
    cudaGetSymbolAddress((void**)&Hl, g_Hl);
    cudaGetSymbolAddress((void**)&Wh, g_Wh);
    cudaGetSymbolAddress((void**)&Wl, g_Wl);
    cudaGetSymbolAddress((void**)&Ch, g_Ch);
    cudaGetSymbolAddress((void**)&Cl, g_Cl);
    cudaGetSymbolAddress((void**)&KtH, g_KthH);
    cudaGetSymbolAddress((void**)&KtL, g_KthL);
    cudaGetSymbolAddress((void**)&Vh, g_VhS);
    cudaGetSymbolAddress((void**)&Vl, g_VlS);

    cudaFuncSetAttribute(gemm_pre, cudaFuncAttributeMaxDynamicSharedMemorySize, GEMM_SMEM);
    cudaFuncSetAttribute(attn_tc_kernel, cudaFuncAttributeMaxDynamicSharedMemorySize, ATTN_SMEM);

    // pre-split hidden
    split_mat<<<(NTOK*HID/4 + 255)/256, 256>>>(hidden, Hh, Hl, NTOK*HID/4);

    // Q projection
    split_mat<<<(HID*QCOLS/4 + 255)/256, 256>>>(Wq, Wh, Wl, HID*QCOLS/4);
    gemm_pre<<<dim3(QCOLS/128, NTOK/128), 256, GEMM_SMEM>>>(Hh, Hl, Wh, Wl, Qp, NTOK, QCOLS, HID);
    // K projection
    split_mat<<<(HID*KVCOLS/4 + 255)/256, 256>>>(Wk, Wh, Wl, HID*KVCOLS/4);
    gemm_pre<<<dim3(KVCOLS/128, NTOK/128), 256, GEMM_SMEM>>>(Hh, Hl, Wh, Wl, Kp, NTOK, KVCOLS, HID);
    // V projection
    split_mat<<<(HID*KVCOLS/4 + 255)/256, 256>>>(Wv, Wh, Wl, HID*KVCOLS/4);
    gemm_pre<<<dim3(KVCOLS/128, NTOK/128), 256, GEMM_SMEM>>>(Hh, Hl, Wh, Wl, Vp, NTOK, KVCOLS, HID);

    // RMSNorm + RoPE (fp32 in-place)
    rmsrope_kernel<<<NTOK * NH, 128>>>(Qp, qw, pos, NH);
    rmsrope_kernel<<<NTOK * NKV, 128>>>(Kp, kw, pos, NKV);

    // pre-split K (transposed) and V
    split_k_trans<<<BATCH*NKV*HD, 256>>>(Kp, KtH, KtL);
    split_mat<<<(NTOK*KVCOLS/4 + 255)/256, 256>>>(Vp, Vh, Vl, NTOK*KVCOLS/4);

    // flash attention
    attn_tc_kernel<<<dim3(SEQ/128, NH, BATCH), 256, ATTN_SMEM>>>(Qp, KtH, KtL, Vh, Vl, Cp);

    // output projection
    split_mat<<<(NTOK*QCOLS/4 + 255)/256, 256>>>(Cp, Ch, Cl, NTOK*QCOLS/4);
    split_mat<<<(QCOLS*HID/4 + 255)/256, 256>>>(Wo, Wh, Wl, QCOLS*HID/4);
    gemm_pre<<<dim3(HID/128, NTOK/128), 256, GEMM_SMEM>>>(Ch, Cl, Wh, Wl, out, NTOK, HID, QCOLS);
}